// round 1
// baseline (speedup 1.0000x reference)
#include <cuda_runtime.h>
#include <math.h>

#define MAXN 100000
#define MAXE 1600000
#define MAXG 128

// ---------------- scratch (static __device__ — no allocation) ----------------
__device__ int   g_deg[MAXN];
__device__ float g_dinv[MAXN];
__device__ int   g_rowptr[MAXN + 1];
__device__ int   g_cursor[MAXN];
__device__ int   g_col[MAXE];
__device__ float g_ew[MAXE];
__device__ int   g_bsums[256];
__device__ float g_X1[(size_t)MAXN * 64];
__device__ float g_X2[(size_t)MAXN * 64];
__device__ float g_H1[(size_t)MAXN * 64];
__device__ float g_H2[(size_t)MAXN * 64];
__device__ float g_gsum[MAXG * 64];
__device__ int   g_gcnt[MAXG];

// ---------------- setup kernels ----------------
__global__ void zero_kernel(int n, int G) {
    int i = blockIdx.x * 256 + threadIdx.x;
    if (i < n) g_deg[i] = 0;
    if (i < G * 64) g_gsum[i] = 0.f;
    if (i < G) g_gcnt[i] = 0;
}

__global__ void deg_kernel(const int* __restrict__ dst, int e) {
    int i = blockIdx.x * 256 + threadIdx.x;
    if (i < e) atomicAdd(&g_deg[dst[i]], 1);
}

// per-1024-chunk exclusive scan of g_deg into g_rowptr; block sums to g_bsums
__global__ void scan_block_kernel(int n) {
    __shared__ int wsum[8];
    const int tid = threadIdx.x, lane = tid & 31, wid = tid >> 5;
    const int base = blockIdx.x * 1024 + tid * 4;
    int v[4]; int s = 0;
#pragma unroll
    for (int j = 0; j < 4; j++) { int i = base + j; v[j] = (i < n) ? g_deg[i] : 0; s += v[j]; }
    int inc = s;
#pragma unroll
    for (int o = 1; o < 32; o <<= 1) { int t = __shfl_up_sync(0xFFFFFFFFu, inc, o); if (lane >= o) inc += t; }
    if (lane == 31) wsum[wid] = inc;
    __syncthreads();
    if (wid == 0) {
        int w = (lane < 8) ? wsum[lane] : 0;
#pragma unroll
        for (int o = 1; o < 8; o <<= 1) { int t = __shfl_up_sync(0xFFFFFFFFu, w, o); if (lane >= o) w += t; }
        if (lane < 8) wsum[lane] = w;
    }
    __syncthreads();
    int run = inc - s + (wid > 0 ? wsum[wid - 1] : 0);
#pragma unroll
    for (int j = 0; j < 4; j++) { int i = base + j; if (i < n) g_rowptr[i] = run; run += v[j]; }
    if (tid == 0) g_bsums[blockIdx.x] = wsum[7];
}

__global__ void scan_mid_kernel(int nb) {  // nb <= 128, one block of 128
    __shared__ int ws[4];
    int tid = threadIdx.x, lane = tid & 31, wid = tid >> 5;
    int v = (tid < nb) ? g_bsums[tid] : 0;
    int inc = v;
#pragma unroll
    for (int o = 1; o < 32; o <<= 1) { int t = __shfl_up_sync(0xFFFFFFFFu, inc, o); if (lane >= o) inc += t; }
    if (lane == 31) ws[wid] = inc;
    __syncthreads();
    int off = 0;
    for (int i = 0; i < wid; i++) off += ws[i];
    if (tid < nb) g_bsums[tid] = off + inc - v;
}

__global__ void finish_kernel(int n, int e) {
    int i = blockIdx.x * 256 + threadIdx.x;
    if (i < n) {
        int r = g_rowptr[i] + g_bsums[i >> 10];
        g_rowptr[i] = r;
        g_cursor[i] = r;
        int d = g_deg[i];
        g_dinv[i] = (d > 0) ? 1.0f / sqrtf((float)d) : 1.0f;
    }
    if (i == 0) g_rowptr[n] = e;
}

__global__ void fill_kernel(const int* __restrict__ src, const int* __restrict__ dst, int e) {
    int i = blockIdx.x * 256 + threadIdx.x;
    if (i < e) {
        int d = dst[i], s = src[i];
        int p = atomicAdd(&g_cursor[d], 1);
        g_col[p] = s;
        g_ew[p] = g_dinv[s];
    }
}

// ---------------- gather aggregations (CSR, one warp per node) ----------------
// out = alpha * dinv_i * sum_e w_e * f[src_e]  (+ beta * extra_i)
__global__ void aggr64_kernel(const float* __restrict__ f, const float* __restrict__ extra,
                              float* __restrict__ out, float alpha, float beta, int n) {
    int node = blockIdx.x * 8 + (threadIdx.x >> 5);
    if (node >= n) return;
    int lane = threadIdx.x & 31;
    int beg = g_rowptr[node], end = g_rowptr[node + 1];
    float ax = 0.f, ay = 0.f;
    int e = beg;
    for (; e + 1 < end; e += 2) {
        int s0 = g_col[e], s1 = g_col[e + 1];
        float w0 = g_ew[e], w1 = g_ew[e + 1];
        float2 v0 = *(const float2*)(f + (size_t)s0 * 64 + lane * 2);
        float2 v1 = *(const float2*)(f + (size_t)s1 * 64 + lane * 2);
        ax = fmaf(w0, v0.x, ax); ay = fmaf(w0, v0.y, ay);
        ax = fmaf(w1, v1.x, ax); ay = fmaf(w1, v1.y, ay);
    }
    if (e < end) {
        int s = g_col[e]; float w = g_ew[e];
        float2 v = *(const float2*)(f + (size_t)s * 64 + lane * 2);
        ax = fmaf(w, v.x, ax); ay = fmaf(w, v.y, ay);
    }
    float di = g_dinv[node];
    float rx = alpha * di * ax, ry = alpha * di * ay;
    if (extra) {
        float2 ex = *(const float2*)(extra + (size_t)node * 64 + lane * 2);
        rx = fmaf(beta, ex.x, rx); ry = fmaf(beta, ex.y, ry);
    }
    *(float2*)(out + (size_t)node * 64 + lane * 2) = make_float2(rx, ry);
}

__global__ void aggr16_kernel(const float* __restrict__ f, const float* __restrict__ extra,
                              float* __restrict__ out, float alpha, float beta, int n) {
    int node = blockIdx.x * 8 + (threadIdx.x >> 5);
    if (node >= n) return;
    int lane = threadIdx.x & 31;
    int c = lane & 15, half = lane >> 4;
    int beg = g_rowptr[node], end = g_rowptr[node + 1];
    float acc = 0.f;
    for (int e = beg + half; e < end; e += 2) {
        int s = g_col[e]; float w = g_ew[e];
        acc = fmaf(w, f[(size_t)s * 16 + c], acc);
    }
    acc += __shfl_down_sync(0xFFFFFFFFu, acc, 16);
    if (half == 0) {
        float di = g_dinv[node];
        float r = alpha * di * acc;
        if (extra) r = fmaf(beta, extra[(size_t)node * 16 + c], r);
        out[(size_t)node * 16 + c] = r;
    }
}

// EdgeConv combine: out_i = relu(U_i - min_{j->i} V_j), 0 if no in-edges
__global__ void edge_min_kernel(const float* __restrict__ U, const float* __restrict__ V,
                                float* __restrict__ out, int n) {
    int node = blockIdx.x * 8 + (threadIdx.x >> 5);
    if (node >= n) return;
    int lane = threadIdx.x & 31;
    int beg = g_rowptr[node], end = g_rowptr[node + 1];
    float mx = 3.4e38f, my = 3.4e38f;
    int e = beg;
    for (; e + 1 < end; e += 2) {
        int s0 = g_col[e], s1 = g_col[e + 1];
        float2 v0 = *(const float2*)(V + (size_t)s0 * 64 + lane * 2);
        float2 v1 = *(const float2*)(V + (size_t)s1 * 64 + lane * 2);
        mx = fminf(mx, fminf(v0.x, v1.x)); my = fminf(my, fminf(v0.y, v1.y));
    }
    if (e < end) {
        int s = g_col[e];
        float2 v = *(const float2*)(V + (size_t)s * 64 + lane * 2);
        mx = fminf(mx, v.x); my = fminf(my, v.y);
    }
    float2 r;
    if (end > beg) {
        float2 u = *(const float2*)(U + (size_t)node * 64 + lane * 2);
        r.x = fmaxf(u.x - mx, 0.f); r.y = fmaxf(u.y - my, 0.f);
    } else { r.x = 0.f; r.y = 0.f; }
    *(float2*)(out + (size_t)node * 64 + lane * 2) = r;
}

// ---------------- GEMMs (SIMT fp32, W broadcast from smem) ----------------
// out = relu(X0@W[0] + X1@W[1] + X2@W[2] + b), 64-node tile, 128 threads
template <int D>
__global__ void __launch_bounds__(128) cheb_gemm_kernel(
    const float* __restrict__ X0, const float* __restrict__ X1,
    const float* __restrict__ X2, const float* __restrict__ W,
    const float* __restrict__ b, float* __restrict__ out, int n) {
    __shared__ __align__(16) float Xs[64][D + 1];
    __shared__ __align__(16) float Ws[D][64];
    const int tid = threadIdx.x;
    const int m = tid & 63;
    const int cbase = (tid >> 6) * 32;
    const int node0 = blockIdx.x * 64;
    const int node = node0 + m;
    float acc[32];
#pragma unroll
    for (int c = 0; c < 32; c++) acc[c] = __ldg(&b[cbase + c]);
    const float* Xsrc[3] = {X0, X1, X2};
#pragma unroll
    for (int j = 0; j < 3; j++) {
        __syncthreads();
        const float* Xj = Xsrc[j];
        for (int i = tid; i < 64 * D; i += 128) {
            int r = i / D, c2 = i - r * D;
            int nn = node0 + r;
            Xs[r][c2] = (nn < n) ? Xj[(size_t)nn * D + c2] : 0.f;
            Ws[i >> 6][i & 63] = W[j * D * 64 + i];
        }
        __syncthreads();
#pragma unroll
        for (int k = 0; k < D; k++) {
            float x = Xs[m][k];
#pragma unroll
            for (int c = 0; c < 32; c += 4) {
                const float4 w = *(const float4*)&Ws[k][cbase + c];
                acc[c]     = fmaf(x, w.x, acc[c]);
                acc[c + 1] = fmaf(x, w.y, acc[c + 1]);
                acc[c + 2] = fmaf(x, w.z, acc[c + 2]);
                acc[c + 3] = fmaf(x, w.w, acc[c + 3]);
            }
        }
    }
    if (node < n) {
#pragma unroll
        for (int c = 0; c < 32; c += 4) {
            float4 r;
            r.x = fmaxf(acc[c], 0.f);     r.y = fmaxf(acc[c + 1], 0.f);
            r.z = fmaxf(acc[c + 2], 0.f); r.w = fmaxf(acc[c + 3], 0.f);
            *(float4*)&out[(size_t)node * 64 + cbase + c] = r;
        }
    }
}

// U = X@(Wt+Wp)+bt+bp, V = X@Wt  (shared X tile, two weight passes)
__global__ void __launch_bounds__(128) edge_gemm_kernel(
    const float* __restrict__ X, const float* __restrict__ Wt, const float* __restrict__ Wp,
    const float* __restrict__ bt, const float* __restrict__ bp,
    float* __restrict__ U, float* __restrict__ V, int n) {
    __shared__ __align__(16) float Xs[64][65];
    __shared__ __align__(16) float Ws[64][64];
    const int tid = threadIdx.x;
    const int m = tid & 63;
    const int cbase = (tid >> 6) * 32;
    const int node0 = blockIdx.x * 64;
    const int node = node0 + m;

    for (int i = tid; i < 64 * 64; i += 128) {
        int r = i >> 6, c2 = i & 63;
        int nn = node0 + r;
        Xs[r][c2] = (nn < n) ? X[(size_t)nn * 64 + c2] : 0.f;
        Ws[r][c2] = Wt[i] + Wp[i];
    }
    __syncthreads();

    float acc[32];
#pragma unroll
    for (int c = 0; c < 32; c++) acc[c] = __ldg(&bt[cbase + c]) + __ldg(&bp[cbase + c]);
#pragma unroll
    for (int k = 0; k < 64; k++) {
        float x = Xs[m][k];
#pragma unroll
        for (int c = 0; c < 32; c += 4) {
            const float4 w = *(const float4*)&Ws[k][cbase + c];
            acc[c]     = fmaf(x, w.x, acc[c]);
            acc[c + 1] = fmaf(x, w.y, acc[c + 1]);
            acc[c + 2] = fmaf(x, w.z, acc[c + 2]);
            acc[c + 3] = fmaf(x, w.w, acc[c + 3]);
        }
    }
    if (node < n) {
#pragma unroll
        for (int c = 0; c < 32; c += 4)
            *(float4*)&U[(size_t)node * 64 + cbase + c] =
                make_float4(acc[c], acc[c + 1], acc[c + 2], acc[c + 3]);
    }
    __syncthreads();
    for (int i = tid; i < 64 * 64; i += 128) Ws[i >> 6][i & 63] = Wt[i];
    __syncthreads();
#pragma unroll
    for (int c = 0; c < 32; c++) acc[c] = 0.f;
#pragma unroll
    for (int k = 0; k < 64; k++) {
        float x = Xs[m][k];
#pragma unroll
        for (int c = 0; c < 32; c += 4) {
            const float4 w = *(const float4*)&Ws[k][cbase + c];
            acc[c]     = fmaf(x, w.x, acc[c]);
            acc[c + 1] = fmaf(x, w.y, acc[c + 1]);
            acc[c + 2] = fmaf(x, w.z, acc[c + 2]);
            acc[c + 3] = fmaf(x, w.w, acc[c + 3]);
        }
    }
    if (node < n) {
#pragma unroll
        for (int c = 0; c < 32; c += 4)
            *(float4*)&V[(size_t)node * 64 + cbase + c] =
                make_float4(acc[c], acc[c + 1], acc[c + 2], acc[c + 3]);
    }
}

// ---------------- pooling ----------------
__global__ void pool_kernel(const float* __restrict__ h, const int* __restrict__ gid, int n) {
    int nw = gridDim.x * (blockDim.x >> 5);
    int w = blockIdx.x * (blockDim.x >> 5) + (threadIdx.x >> 5);
    int lane = threadIdx.x & 31;
    int chunk = (n + nw - 1) / nw;
    int beg = w * chunk, end = min(n, beg + chunk);
    if (beg >= end) return;
    float sx = 0.f, sy = 0.f;
    int cur = gid[beg]; int cnt = 0;
    for (int i = beg; i < end; i++) {
        int g = gid[i];
        if (g != cur) {
            atomicAdd(&g_gsum[cur * 64 + lane * 2], sx);
            atomicAdd(&g_gsum[cur * 64 + lane * 2 + 1], sy);
            if (lane == 0) atomicAdd(&g_gcnt[cur], cnt);
            sx = 0.f; sy = 0.f; cnt = 0; cur = g;
        }
        float2 v = *(const float2*)(h + (size_t)i * 64 + lane * 2);
        sx += v.x; sy += v.y; cnt++;
    }
    atomicAdd(&g_gsum[cur * 64 + lane * 2], sx);
    atomicAdd(&g_gsum[cur * 64 + lane * 2 + 1], sy);
    if (lane == 0) atomicAdd(&g_gcnt[cur], cnt);
}

__global__ void finalize_kernel(float* __restrict__ out, int G) {
    int i = blockIdx.x * 256 + threadIdx.x;
    if (i < G * 64) {
        int c = g_gcnt[i >> 6];
        out[i] = g_gsum[i] / (c > 0 ? (float)c : 1.0f);
    }
}

// ---------------- launch ----------------
extern "C" void kernel_launch(void* const* d_in, const int* in_sizes, int n_in,
                              void* d_out, int out_size) {
    const float* feat = (const float*)d_in[0];
    const int*   src  = (const int*)d_in[1];
    const int*   dst  = (const int*)d_in[2];
    const int*   gid  = (const int*)d_in[3];
    const float* W1 = (const float*)d_in[4];  const float* b1 = (const float*)d_in[5];
    const float* W2 = (const float*)d_in[6];  const float* b2 = (const float*)d_in[7];
    const float* W3 = (const float*)d_in[8];  const float* b3 = (const float*)d_in[9];
    const float* Wt1 = (const float*)d_in[10]; const float* bt1 = (const float*)d_in[11];
    const float* Wp1 = (const float*)d_in[12]; const float* bp1 = (const float*)d_in[13];
    const float* Wt2 = (const float*)d_in[14]; const float* bt2 = (const float*)d_in[15];
    const float* Wp2 = (const float*)d_in[16]; const float* bp2 = (const float*)d_in[17];
    float* out = (float*)d_out;

    const int n = in_sizes[0] / 16;
    const int e = in_sizes[1];
    const int G = out_size / 64;

    const int zb = (max(n, G * 64) + 255) / 256;
    const int eb = (e + 255) / 256;
    const int nb = (n + 255) / 256;
    const int sb = (n + 1023) / 1024;
    const int wb = (n + 7) / 8;           // warp-per-node kernels, 256 threads
    const int gb = (n + 63) / 64;         // gemm tiles

    // CSR + degree
    zero_kernel<<<zb, 256>>>(n, G);
    deg_kernel<<<eb, 256>>>(dst, e);
    scan_block_kernel<<<sb, 256>>>(n);
    scan_mid_kernel<<<1, 128>>>(sb);
    finish_kernel<<<nb, 256>>>(n, e);
    fill_kernel<<<eb, 256>>>(src, dst, e);

    // Layer 1: ChebConv(16->64)   X1 = -aggr(X0), X2 = -2*aggr(X1) - X0
    aggr16_kernel<<<wb, 256>>>(feat, nullptr, g_X1, -1.f, 0.f, n);
    aggr16_kernel<<<wb, 256>>>(g_X1, feat, g_X2, -2.f, -1.f, n);
    cheb_gemm_kernel<16><<<gb, 128>>>(feat, g_X1, g_X2, W1, b1, g_H1, n);

    // Layer 2: EdgeConv
    edge_gemm_kernel<<<gb, 128>>>(g_H1, Wt1, Wp1, bt1, bp1, g_X1, g_X2, n);
    edge_min_kernel<<<wb, 256>>>(g_X1, g_X2, g_H2, n);

    // Layer 3: ChebConv(64->64)
    aggr64_kernel<<<wb, 256>>>(g_H2, nullptr, g_X1, -1.f, 0.f, n);
    aggr64_kernel<<<wb, 256>>>(g_X1, g_H2, g_X2, -2.f, -1.f, n);
    cheb_gemm_kernel<64><<<gb, 128>>>(g_H2, g_X1, g_X2, W2, b2, g_H1, n);

    // Layer 4: EdgeConv
    edge_gemm_kernel<<<gb, 128>>>(g_H1, Wt2, Wp2, bt2, bp2, g_X1, g_X2, n);
    edge_min_kernel<<<wb, 256>>>(g_X1, g_X2, g_H2, n);

    // Layer 5: ChebConv(64->64)
    aggr64_kernel<<<wb, 256>>>(g_H2, nullptr, g_X1, -1.f, 0.f, n);
    aggr64_kernel<<<wb, 256>>>(g_X1, g_H2, g_X2, -2.f, -1.f, n);
    cheb_gemm_kernel<64><<<gb, 128>>>(g_H2, g_X1, g_X2, W3, b3, g_H1, n);

    // Mean pool per graph
    pool_kernel<<<256, 256>>>(g_H1, gid, n);
    finalize_kernel<<<(G * 64 + 255) / 256, 256>>>(out, G);
}

// round 3
// speedup vs baseline: 1.2551x; 1.2551x over previous
#include <cuda_runtime.h>
#include <math.h>

#define MAXN 100000
#define MAXE 1600000
#define MAXG 128

// ---------------- scratch (static __device__, zero-initialized at load) ----------------
__device__ int   g_deg[MAXN];          // zeroed at END of each replay (and initially 0)
__device__ float g_dinv[MAXN];
__device__ int   g_rowptr[MAXN + 1];
__device__ int   g_cursor[MAXN];
__device__ int   g_col[MAXE];
__device__ float g_ew[MAXE];
__device__ float g_B1[(size_t)MAXN * 64];
__device__ float g_B2[(size_t)MAXN * 64];
__device__ float g_B3[(size_t)MAXN * 64];
__device__ float g_B4[(size_t)MAXN * 64];
__device__ float g_gsum[MAXG * 64];
__device__ int   g_gcnt[MAXG];

// ---------------- CSR build ----------------
__global__ void deg_kernel(const int* __restrict__ dst, int e) {
    int i = blockIdx.x * 256 + threadIdx.x;
    if (i < e) atomicAdd(&g_deg[dst[i]], 1);
}

// Single-block scan: rowptr (exclusive scan of deg), cursor, dinv, rowptr[n]=e.
// Also zeroes pooling accumulators for this replay.
__global__ void __launch_bounds__(1024) csr_scan_kernel(int n, int e, int G) {
    __shared__ int wsums[32];
    __shared__ int s_running;
    __shared__ int s_tile_total;
    const int tid = threadIdx.x, lane = tid & 31, wid = tid >> 5;
    if (tid == 0) s_running = 0;
    for (int i = tid; i < G * 64; i += 1024) g_gsum[i] = 0.f;
    for (int i = tid; i < G; i += 1024) g_gcnt[i] = 0;
    __syncthreads();
    const int ntiles = (n + 4095) >> 12;
    for (int t = 0; t < ntiles; t++) {
        const int base = (t << 12) + tid * 4;
        int v[4]; int s = 0;
#pragma unroll
        for (int j = 0; j < 4; j++) { int i = base + j; v[j] = (i < n) ? g_deg[i] : 0; s += v[j]; }
        int inc = s;
#pragma unroll
        for (int o = 1; o < 32; o <<= 1) { int x = __shfl_up_sync(0xFFFFFFFFu, inc, o); if (lane >= o) inc += x; }
        if (lane == 31) wsums[wid] = inc;
        __syncthreads();
        if (wid == 0) {
            int w = wsums[lane];
            int winc = w;
#pragma unroll
            for (int o = 1; o < 32; o <<= 1) { int x = __shfl_up_sync(0xFFFFFFFFu, winc, o); if (lane >= o) winc += x; }
            wsums[lane] = winc - w;          // exclusive warp prefix
            if (lane == 31) s_tile_total = winc;
        }
        __syncthreads();
        int off = s_running + wsums[wid] + (inc - s);
#pragma unroll
        for (int j = 0; j < 4; j++) {
            int i = base + j;
            if (i < n) {
                g_rowptr[i] = off;
                g_cursor[i] = off;
                int d = v[j];
                g_dinv[i] = (d > 0) ? rsqrtf((float)d) : 1.0f;
                off += d;
            }
        }
        __syncthreads();
        if (tid == 0) s_running += s_tile_total;
    }
    if (tid == 0) g_rowptr[n] = e;
}

__global__ void fill_kernel(const int* __restrict__ src, const int* __restrict__ dst, int e) {
    int i = blockIdx.x * 256 + threadIdx.x;
    if (i < e) {
        int d = dst[i], s = src[i];
        int p = atomicAdd(&g_cursor[d], 1);
        g_col[p] = s;
        g_ew[p] = g_dinv[s];
    }
}

// ---------------- gathers: warp = 1 node; 2 edges x 16 lanes x float4 ----------------
// out = alpha * dinv_i * sum_e w_e * f[col_e]  (+ beta * extra_i),  64-dim rows
__global__ void __launch_bounds__(256) aggr64_kernel(
    const float* __restrict__ f, const float* __restrict__ extra,
    float* __restrict__ out, float alpha, float beta, int n) {
    int node = blockIdx.x * 8 + (threadIdx.x >> 5);
    if (node >= n) return;
    const int lane = threadIdx.x & 31;
    const int sub = lane >> 4;       // which edge of the pair
    const int c = (lane & 15) * 4;   // column base (float4)
    const int beg = g_rowptr[node], end = g_rowptr[node + 1];
    float4 acc = make_float4(0.f, 0.f, 0.f, 0.f);
    for (int e = beg; e < end; e += 4) {
        int e0 = e + sub, e1 = e + 2 + sub;
        bool v0 = e0 < end, v1 = e1 < end;
        int   s0 = v0 ? g_col[e0] : 0;
        float w0 = v0 ? g_ew[e0] : 0.f;
        int   s1 = v1 ? g_col[e1] : 0;
        float w1 = v1 ? g_ew[e1] : 0.f;
        float4 x0 = *(const float4*)(f + (size_t)s0 * 64 + c);
        float4 x1 = *(const float4*)(f + (size_t)s1 * 64 + c);
        acc.x = fmaf(w0, x0.x, acc.x); acc.y = fmaf(w0, x0.y, acc.y);
        acc.z = fmaf(w0, x0.z, acc.z); acc.w = fmaf(w0, x0.w, acc.w);
        acc.x = fmaf(w1, x1.x, acc.x); acc.y = fmaf(w1, x1.y, acc.y);
        acc.z = fmaf(w1, x1.z, acc.z); acc.w = fmaf(w1, x1.w, acc.w);
    }
    acc.x += __shfl_xor_sync(0xFFFFFFFFu, acc.x, 16);
    acc.y += __shfl_xor_sync(0xFFFFFFFFu, acc.y, 16);
    acc.z += __shfl_xor_sync(0xFFFFFFFFu, acc.z, 16);
    acc.w += __shfl_xor_sync(0xFFFFFFFFu, acc.w, 16);
    if (sub == 0) {
        float s = alpha * g_dinv[node];
        float4 r = make_float4(s * acc.x, s * acc.y, s * acc.z, s * acc.w);
        if (extra) {
            float4 ex = *(const float4*)(extra + (size_t)node * 64 + c);
            r.x = fmaf(beta, ex.x, r.x); r.y = fmaf(beta, ex.y, r.y);
            r.z = fmaf(beta, ex.z, r.z); r.w = fmaf(beta, ex.w, r.w);
        }
        *(float4*)(out + (size_t)node * 64 + c) = r;
    }
}

// 16-dim variant: 8 edges x 4 lanes x float4
__global__ void __launch_bounds__(256) aggr16_kernel(
    const float* __restrict__ f, const float* __restrict__ extra,
    float* __restrict__ out, float alpha, float beta, int n) {
    int node = blockIdx.x * 8 + (threadIdx.x >> 5);
    if (node >= n) return;
    const int lane = threadIdx.x & 31;
    const int sub = lane >> 2;       // edge within group of 8
    const int c = (lane & 3) * 4;
    const int beg = g_rowptr[node], end = g_rowptr[node + 1];
    float4 acc = make_float4(0.f, 0.f, 0.f, 0.f);
    for (int e = beg; e < end; e += 8) {
        int ee = e + sub;
        bool v = ee < end;
        int   s = v ? g_col[ee] : 0;
        float w = v ? g_ew[ee] : 0.f;
        float4 x = *(const float4*)(f + (size_t)s * 16 + c);
        acc.x = fmaf(w, x.x, acc.x); acc.y = fmaf(w, x.y, acc.y);
        acc.z = fmaf(w, x.z, acc.z); acc.w = fmaf(w, x.w, acc.w);
    }
#pragma unroll
    for (int o = 4; o < 32; o <<= 1) {
        acc.x += __shfl_xor_sync(0xFFFFFFFFu, acc.x, o);
        acc.y += __shfl_xor_sync(0xFFFFFFFFu, acc.y, o);
        acc.z += __shfl_xor_sync(0xFFFFFFFFu, acc.z, o);
        acc.w += __shfl_xor_sync(0xFFFFFFFFu, acc.w, o);
    }
    if (lane < 4) {
        float s = alpha * g_dinv[node];
        float4 r = make_float4(s * acc.x, s * acc.y, s * acc.z, s * acc.w);
        if (extra) {
            float4 ex = *(const float4*)(extra + (size_t)node * 16 + c);
            r.x = fmaf(beta, ex.x, r.x); r.y = fmaf(beta, ex.y, r.y);
            r.z = fmaf(beta, ex.z, r.z); r.w = fmaf(beta, ex.w, r.w);
        }
        *(float4*)(out + (size_t)node * 16 + c) = r;
    }
}

// EdgeConv combine: out_i = relu(U_i - min_{j->i} V_j), 0 if no in-edges
__global__ void __launch_bounds__(256) edge_min_kernel(
    const float* __restrict__ U, const float* __restrict__ V,
    float* __restrict__ out, int n) {
    int node = blockIdx.x * 8 + (threadIdx.x >> 5);
    if (node >= n) return;
    const int lane = threadIdx.x & 31;
    const int sub = lane >> 4;
    const int c = (lane & 15) * 4;
    const int beg = g_rowptr[node], end = g_rowptr[node + 1];
    float4 mn = make_float4(3.4e38f, 3.4e38f, 3.4e38f, 3.4e38f);
    for (int e = beg; e < end; e += 4) {
        int e0 = e + sub, e1 = e + 2 + sub;
        if (e0 < end) {
            int s0 = g_col[e0];
            float4 x = *(const float4*)(V + (size_t)s0 * 64 + c);
            mn.x = fminf(mn.x, x.x); mn.y = fminf(mn.y, x.y);
            mn.z = fminf(mn.z, x.z); mn.w = fminf(mn.w, x.w);
        }
        if (e1 < end) {
            int s1 = g_col[e1];
            float4 x = *(const float4*)(V + (size_t)s1 * 64 + c);
            mn.x = fminf(mn.x, x.x); mn.y = fminf(mn.y, x.y);
            mn.z = fminf(mn.z, x.z); mn.w = fminf(mn.w, x.w);
        }
    }
    mn.x = fminf(mn.x, __shfl_xor_sync(0xFFFFFFFFu, mn.x, 16));
    mn.y = fminf(mn.y, __shfl_xor_sync(0xFFFFFFFFu, mn.y, 16));
    mn.z = fminf(mn.z, __shfl_xor_sync(0xFFFFFFFFu, mn.z, 16));
    mn.w = fminf(mn.w, __shfl_xor_sync(0xFFFFFFFFu, mn.w, 16));
    if (sub == 0) {
        float4 r = make_float4(0.f, 0.f, 0.f, 0.f);
        if (end > beg) {
            float4 u = *(const float4*)(U + (size_t)node * 64 + c);
            r.x = fmaxf(u.x - mn.x, 0.f); r.y = fmaxf(u.y - mn.y, 0.f);
            r.z = fmaxf(u.z - mn.z, 0.f); r.w = fmaxf(u.w - mn.w, 0.f);
        }
        *(float4*)(out + (size_t)node * 64 + c) = r;
    }
}

// ---------------- fused GEMM: Cheb projection + EdgeConv U/V, 64-node tile ----------------
// H = relu(X0@W[0]+X1@W[1]+X2@W[2]+b)  (kept in smem only)
// U = H@(Wt+Wp)+bt+bp,  V = H@Wt
template <int D>
__global__ void __launch_bounds__(256) fused_cheb_edge_kernel(
    const float* __restrict__ X0, const float* __restrict__ X1, const float* __restrict__ X2,
    const float* __restrict__ W, const float* __restrict__ b,
    const float* __restrict__ Wt, const float* __restrict__ Wp,
    const float* __restrict__ bt, const float* __restrict__ bp,
    float* __restrict__ U, float* __restrict__ V, int n) {
    __shared__ __align__(16) float XH[64][68];   // X tile per pass, then H tile
    __shared__ __align__(16) float Ws[64][64];
    const int tid = threadIdx.x;
    const int m = tid >> 2;              // node row in tile
    const int cbase = (tid & 3) * 16;    // 16 output cols per thread
    const int node0 = blockIdx.x * 64;
    const int node = node0 + m;

    float acc[16];
#pragma unroll
    for (int c = 0; c < 16; c++) acc[c] = __ldg(&b[cbase + c]);
    const float* Xsrc[3] = {X0, X1, X2};
#pragma unroll
    for (int j = 0; j < 3; j++) {
        __syncthreads();
        const float* Xj = Xsrc[j];
        for (int i = tid; i < 64 * D; i += 256) {
            int r = i / D, c2 = i - r * D;
            int nn = node0 + r;
            XH[r][c2] = (nn < n) ? Xj[(size_t)nn * D + c2] : 0.f;
        }
        for (int i = tid; i < D * 64; i += 256) Ws[i >> 6][i & 63] = W[j * D * 64 + i];
        __syncthreads();
#pragma unroll
        for (int k = 0; k < D; k++) {
            float x = XH[m][k];
#pragma unroll
            for (int cc = 0; cc < 4; cc++) {
                const float4 w = *(const float4*)&Ws[k][cbase + cc * 4];
                acc[cc * 4 + 0] = fmaf(x, w.x, acc[cc * 4 + 0]);
                acc[cc * 4 + 1] = fmaf(x, w.y, acc[cc * 4 + 1]);
                acc[cc * 4 + 2] = fmaf(x, w.z, acc[cc * 4 + 2]);
                acc[cc * 4 + 3] = fmaf(x, w.w, acc[cc * 4 + 3]);
            }
        }
    }
    __syncthreads();
    // relu -> H tile in smem; load edge weights Wt+Wp
#pragma unroll
    for (int cc = 0; cc < 4; cc++) {
        float4 h;
        h.x = fmaxf(acc[cc * 4 + 0], 0.f); h.y = fmaxf(acc[cc * 4 + 1], 0.f);
        h.z = fmaxf(acc[cc * 4 + 2], 0.f); h.w = fmaxf(acc[cc * 4 + 3], 0.f);
        *(float4*)&XH[m][cbase + cc * 4] = h;
    }
    for (int i = tid; i < 4096; i += 256) Ws[i >> 6][i & 63] = Wt[i] + Wp[i];
    __syncthreads();

#pragma unroll
    for (int c = 0; c < 16; c++) acc[c] = __ldg(&bt[cbase + c]) + __ldg(&bp[cbase + c]);
#pragma unroll
    for (int k = 0; k < 64; k++) {
        float x = XH[m][k];
#pragma unroll
        for (int cc = 0; cc < 4; cc++) {
            const float4 w = *(const float4*)&Ws[k][cbase + cc * 4];
            acc[cc * 4 + 0] = fmaf(x, w.x, acc[cc * 4 + 0]);
            acc[cc * 4 + 1] = fmaf(x, w.y, acc[cc * 4 + 1]);
            acc[cc * 4 + 2] = fmaf(x, w.z, acc[cc * 4 + 2]);
            acc[cc * 4 + 3] = fmaf(x, w.w, acc[cc * 4 + 3]);
        }
    }
    if (node < n) {
#pragma unroll
        for (int cc = 0; cc < 4; cc++)
            *(float4*)&U[(size_t)node * 64 + cbase + cc * 4] =
                make_float4(acc[cc * 4], acc[cc * 4 + 1], acc[cc * 4 + 2], acc[cc * 4 + 3]);
    }
    __syncthreads();
    for (int i = tid; i < 4096; i += 256) Ws[i >> 6][i & 63] = Wt[i];
    __syncthreads();
#pragma unroll
    for (int c = 0; c < 16; c++) acc[c] = 0.f;
#pragma unroll
    for (int k = 0; k < 64; k++) {
        float x = XH[m][k];
#pragma unroll
        for (int cc = 0; cc < 4; cc++) {
            const float4 w = *(const float4*)&Ws[k][cbase + cc * 4];
            acc[cc * 4 + 0] = fmaf(x, w.x, acc[cc * 4 + 0]);
            acc[cc * 4 + 1] = fmaf(x, w.y, acc[cc * 4 + 1]);
            acc[cc * 4 + 2] = fmaf(x, w.z, acc[cc * 4 + 2]);
            acc[cc * 4 + 3] = fmaf(x, w.w, acc[cc * 4 + 3]);
        }
    }
    if (node < n) {
#pragma unroll
        for (int cc = 0; cc < 4; cc++)
            *(float4*)&V[(size_t)node * 64 + cbase + cc * 4] =
                make_float4(acc[cc * 4], acc[cc * 4 + 1], acc[cc * 4 + 2], acc[cc * 4 + 3]);
    }
}

// Final Cheb layer: out = relu(X0@W0+X1@W1+X2@W2+b)
__global__ void __launch_bounds__(256) cheb_gemm_kernel(
    const float* __restrict__ X0, const float* __restrict__ X1, const float* __restrict__ X2,
    const float* __restrict__ W, const float* __restrict__ b,
    float* __restrict__ out, int n) {
    __shared__ __align__(16) float Xs[64][68];
    __shared__ __align__(16) float Ws[64][64];
    const int tid = threadIdx.x;
    const int m = tid >> 2;
    const int cbase = (tid & 3) * 16;
    const int node0 = blockIdx.x * 64;
    const int node = node0 + m;
    float acc[16];
#pragma unroll
    for (int c = 0; c < 16; c++) acc[c] = __ldg(&b[cbase + c]);
    const float* Xsrc[3] = {X0, X1, X2};
#pragma unroll
    for (int j = 0; j < 3; j++) {
        __syncthreads();
        const float* Xj = Xsrc[j];
        for (int i = tid; i < 4096; i += 256) {
            int r = i >> 6, c2 = i & 63;
            int nn = node0 + r;
            Xs[r][c2] = (nn < n) ? Xj[(size_t)nn * 64 + c2] : 0.f;
            Ws[r][c2] = W[j * 4096 + i];
        }
        __syncthreads();
#pragma unroll
        for (int k = 0; k < 64; k++) {
            float x = Xs[m][k];
#pragma unroll
            for (int cc = 0; cc < 4; cc++) {
                const float4 w = *(const float4*)&Ws[k][cbase + cc * 4];
                acc[cc * 4 + 0] = fmaf(x, w.x, acc[cc * 4 + 0]);
                acc[cc * 4 + 1] = fmaf(x, w.y, acc[cc * 4 + 1]);
                acc[cc * 4 + 2] = fmaf(x, w.z, acc[cc * 4 + 2]);
                acc[cc * 4 + 3] = fmaf(x, w.w, acc[cc * 4 + 3]);
            }
        }
    }
    if (node < n) {
#pragma unroll
        for (int cc = 0; cc < 4; cc++) {
            float4 r;
            r.x = fmaxf(acc[cc * 4 + 0], 0.f); r.y = fmaxf(acc[cc * 4 + 1], 0.f);
            r.z = fmaxf(acc[cc * 4 + 2], 0.f); r.w = fmaxf(acc[cc * 4 + 3], 0.f);
            *(float4*)&out[(size_t)node * 64 + cbase + cc * 4] = r;
        }
    }
}

// ---------------- pooling ----------------
__global__ void pool_kernel(const float* __restrict__ h, const int* __restrict__ gid, int n) {
    int nw = gridDim.x * (blockDim.x >> 5);
    int w = blockIdx.x * (blockDim.x >> 5) + (threadIdx.x >> 5);
    int lane = threadIdx.x & 31;
    int chunk = (n + nw - 1) / nw;
    int beg = w * chunk, end = min(n, beg + chunk);
    if (beg >= end) return;
    float sx = 0.f, sy = 0.f;
    int cur = gid[beg]; int cnt = 0;
    for (int i = beg; i < end; i++) {
        int g = gid[i];
        if (g != cur) {
            atomicAdd(&g_gsum[cur * 64 + lane * 2], sx);
            atomicAdd(&g_gsum[cur * 64 + lane * 2 + 1], sy);
            if (lane == 0) atomicAdd(&g_gcnt[cur], cnt);
            sx = 0.f; sy = 0.f; cnt = 0; cur = g;
        }
        float2 v = *(const float2*)(h + (size_t)i * 64 + lane * 2);
        sx += v.x; sy += v.y; cnt++;
    }
    atomicAdd(&g_gsum[cur * 64 + lane * 2], sx);
    atomicAdd(&g_gsum[cur * 64 + lane * 2 + 1], sy);
    if (lane == 0) atomicAdd(&g_gcnt[cur], cnt);
}

// Write output + reset g_deg for the next replay
__global__ void finalize_kernel(float* __restrict__ out, int G, int n) {
    int i = blockIdx.x * 256 + threadIdx.x;
    if (i < G * 64) {
        int c = g_gcnt[i >> 6];
        out[i] = g_gsum[i] / (c > 0 ? (float)c : 1.0f);
    }
    if (i < n) g_deg[i] = 0;
}

// ---------------- launch ----------------
extern "C" void kernel_launch(void* const* d_in, const int* in_sizes, int n_in,
                              void* d_out, int out_size) {
    const float* feat = (const float*)d_in[0];
    const int*   src  = (const int*)d_in[1];
    const int*   dst  = (const int*)d_in[2];
    const int*   gid  = (const int*)d_in[3];
    const float* W1 = (const float*)d_in[4];  const float* b1 = (const float*)d_in[5];
    const float* W2 = (const float*)d_in[6];  const float* b2 = (const float*)d_in[7];
    const float* W3 = (const float*)d_in[8];  const float* b3 = (const float*)d_in[9];
    const float* Wt1 = (const float*)d_in[10]; const float* bt1 = (const float*)d_in[11];
    const float* Wp1 = (const float*)d_in[12]; const float* bp1 = (const float*)d_in[13];
    const float* Wt2 = (const float*)d_in[14]; const float* bt2 = (const float*)d_in[15];
    const float* Wp2 = (const float*)d_in[16]; const float* bp2 = (const float*)d_in[17];
    float* out = (float*)d_out;

    const int n = in_sizes[0] / 16;
    const int e = in_sizes[1];
    const int G = out_size / 64;

    const int eb = (e + 255) / 256;
    const int wb = (n + 7) / 8;           // warp-per-node kernels, 256 threads
    const int gb = (n + 63) / 64;         // gemm tiles
    const int fb = (max(n, G * 64) + 255) / 256;

    // CSR (g_deg is 0 on entry: static-init on first call, re-zeroed by finalize after)
    deg_kernel<<<eb, 256>>>(dst, e);
    csr_scan_kernel<<<1, 1024>>>(n, e, G);
    fill_kernel<<<eb, 256>>>(src, dst, e);

    // Layer 1 (Cheb 16->64): X1 = -aggr(feat), X2 = -2*aggr(X1) - feat
    aggr16_kernel<<<wb, 256>>>(feat, nullptr, g_B1, -1.f, 0.f, n);
    aggr16_kernel<<<wb, 256>>>(g_B1, feat, g_B2, -2.f, -1.f, n);
    // Layers 1+2 fused GEMMs: H1 (smem only) -> U=g_B3, V=g_B4
    fused_cheb_edge_kernel<16><<<gb, 256>>>(feat, g_B1, g_B2, W1, b1,
                                            Wt1, Wp1, bt1, bp1, g_B3, g_B4, n);
    edge_min_kernel<<<wb, 256>>>(g_B3, g_B4, g_B1, n);   // H2 -> B1

    // Layer 3 (Cheb 64->64)
    aggr64_kernel<<<wb, 256>>>(g_B1, nullptr, g_B2, -1.f, 0.f, n);
    aggr64_kernel<<<wb, 256>>>(g_B2, g_B1, g_B3, -2.f, -1.f, n);
    // Layers 3+4 fused GEMMs: in-place U->B2, V->B3 (row-local, reads precede writes)
    fused_cheb_edge_kernel<64><<<gb, 256>>>(g_B1, g_B2, g_B3, W2, b2,
                                            Wt2, Wp2, bt2, bp2, g_B2, g_B3, n);
    edge_min_kernel<<<wb, 256>>>(g_B2, g_B3, g_B1, n);   // H4 -> B1

    // Layer 5 (Cheb 64->64)
    aggr64_kernel<<<wb, 256>>>(g_B1, nullptr, g_B2, -1.f, 0.f, n);
    aggr64_kernel<<<wb, 256>>>(g_B2, g_B1, g_B3, -2.f, -1.f, n);
    cheb_gemm_kernel<<<gb, 256>>>(g_B1, g_B2, g_B3, W3, b3, g_B4, n);

    // Mean pool per graph
    pool_kernel<<<256, 256>>>(g_B4, gid, n);
    finalize_kernel<<<fb, 256>>>(out, G, n);
}

// round 5
// speedup vs baseline: 14.2586x; 11.3601x over previous
#include <cuda_runtime.h>
#include <math.h>

#define MAXN 100000
#define MAXE 1600000
#define MAXG 128
#define MAXB 1024

// ---------------- scratch (static __device__ — no allocation) ----------------
__device__ int   g_deg[MAXN];
__device__ float g_dinv[MAXN];
__device__ int   g_rowptr[MAXN + 1];
__device__ int   g_cursor[MAXN];
__device__ int   g_col[MAXE];
__device__ float g_ew[MAXE];
__device__ int   g_bsums[MAXB];
__device__ float g_B1[(size_t)MAXN * 64];
__device__ float g_B2[(size_t)MAXN * 64];
__device__ float g_B3[(size_t)MAXN * 64];
__device__ float g_B4[(size_t)MAXN * 64];
__device__ float g_gsum[MAXG * 64];
__device__ int   g_gcnt[MAXG];
__device__ unsigned g_epoch;   // monotonically increasing across replays
__device__ unsigned g_cnt;

// ---------------- grid-wide barrier (all blocks co-resident by construction) ----------------
__device__ __forceinline__ void gsync(int nb) {
    __syncthreads();
    if (threadIdx.x == 0) {
        __threadfence();                       // release
        volatile unsigned* ep = &g_epoch;
        unsigned e = *ep;
        if (atomicAdd(&g_cnt, 1u) == (unsigned)(nb - 1)) {
            g_cnt = 0;
            __threadfence();
            *ep = e + 1;
        } else {
            while (*ep == e) {}
            __threadfence();                   // acquire
        }
    }
    __syncthreads();
}

// ---------------- phase helpers ----------------
// out = alpha * dinv_i * sum_e w_e * f[col_e]  (+ beta * extra_i), 64-dim rows
__device__ void ph_aggr64(const float* __restrict__ f, const float* __restrict__ extra,
                          float* __restrict__ out, float alpha, float beta,
                          int n, int gw, int nwarps) {
    const int lane = threadIdx.x & 31;
    const int sub = lane >> 4;
    const int c = (lane & 15) * 4;
    for (int node = gw; node < n; node += nwarps) {
        const int beg = g_rowptr[node], end = g_rowptr[node + 1];
        float4 acc = make_float4(0.f, 0.f, 0.f, 0.f);
        for (int e = beg; e < end; e += 4) {
            int e0 = e + sub, e1 = e + 2 + sub;
            bool v0 = e0 < end, v1 = e1 < end;
            int   s0 = v0 ? g_col[e0] : 0;
            float w0 = v0 ? g_ew[e0] : 0.f;
            int   s1 = v1 ? g_col[e1] : 0;
            float w1 = v1 ? g_ew[e1] : 0.f;
            float4 x0 = *(const float4*)(f + (size_t)s0 * 64 + c);
            float4 x1 = *(const float4*)(f + (size_t)s1 * 64 + c);
            acc.x = fmaf(w0, x0.x, acc.x); acc.y = fmaf(w0, x0.y, acc.y);
            acc.z = fmaf(w0, x0.z, acc.z); acc.w = fmaf(w0, x0.w, acc.w);
            acc.x = fmaf(w1, x1.x, acc.x); acc.y = fmaf(w1, x1.y, acc.y);
            acc.z = fmaf(w1, x1.z, acc.z); acc.w = fmaf(w1, x1.w, acc.w);
        }
        acc.x += __shfl_xor_sync(0xFFFFFFFFu, acc.x, 16);
        acc.y += __shfl_xor_sync(0xFFFFFFFFu, acc.y, 16);
        acc.z += __shfl_xor_sync(0xFFFFFFFFu, acc.z, 16);
        acc.w += __shfl_xor_sync(0xFFFFFFFFu, acc.w, 16);
        if (sub == 0) {
            float s = alpha * g_dinv[node];
            float4 r = make_float4(s * acc.x, s * acc.y, s * acc.z, s * acc.w);
            if (extra) {
                float4 ex = *(const float4*)(extra + (size_t)node * 64 + c);
                r.x = fmaf(beta, ex.x, r.x); r.y = fmaf(beta, ex.y, r.y);
                r.z = fmaf(beta, ex.z, r.z); r.w = fmaf(beta, ex.w, r.w);
            }
            *(float4*)(out + (size_t)node * 64 + c) = r;
        }
    }
}

__device__ void ph_aggr16(const float* __restrict__ f, const float* __restrict__ extra,
                          float* __restrict__ out, float alpha, float beta,
                          int n, int gw, int nwarps) {
    const int lane = threadIdx.x & 31;
    const int sub = lane >> 2;
    const int c = (lane & 3) * 4;
    for (int node = gw; node < n; node += nwarps) {
        const int beg = g_rowptr[node], end = g_rowptr[node + 1];
        float4 acc = make_float4(0.f, 0.f, 0.f, 0.f);
        for (int e = beg; e < end; e += 8) {
            int ee = e + sub;
            bool v = ee < end;
            int   s = v ? g_col[ee] : 0;
            float w = v ? g_ew[ee] : 0.f;
            float4 x = *(const float4*)(f + (size_t)s * 16 + c);
            acc.x = fmaf(w, x.x, acc.x); acc.y = fmaf(w, x.y, acc.y);
            acc.z = fmaf(w, x.z, acc.z); acc.w = fmaf(w, x.w, acc.w);
        }
#pragma unroll
        for (int o = 4; o < 32; o <<= 1) {
            acc.x += __shfl_xor_sync(0xFFFFFFFFu, acc.x, o);
            acc.y += __shfl_xor_sync(0xFFFFFFFFu, acc.y, o);
            acc.z += __shfl_xor_sync(0xFFFFFFFFu, acc.z, o);
            acc.w += __shfl_xor_sync(0xFFFFFFFFu, acc.w, o);
        }
        if (lane < 4) {
            float s = alpha * g_dinv[node];
            float4 r = make_float4(s * acc.x, s * acc.y, s * acc.z, s * acc.w);
            if (extra) {
                float4 ex = *(const float4*)(extra + (size_t)node * 16 + c);
                r.x = fmaf(beta, ex.x, r.x); r.y = fmaf(beta, ex.y, r.y);
                r.z = fmaf(beta, ex.z, r.z); r.w = fmaf(beta, ex.w, r.w);
            }
            *(float4*)(out + (size_t)node * 16 + c) = r;
        }
    }
}

// out_i = relu(U_i - min_{j->i} V_j), 0 if no in-edges
__device__ void ph_edge_min(const float* __restrict__ U, const float* __restrict__ V,
                            float* __restrict__ out, int n, int gw, int nwarps) {
    const int lane = threadIdx.x & 31;
    const int sub = lane >> 4;
    const int c = (lane & 15) * 4;
    for (int node = gw; node < n; node += nwarps) {
        const int beg = g_rowptr[node], end = g_rowptr[node + 1];
        float4 mn = make_float4(3.4e38f, 3.4e38f, 3.4e38f, 3.4e38f);
        for (int e = beg; e < end; e += 4) {
            int e0 = e + sub, e1 = e + 2 + sub;
            if (e0 < end) {
                int s0 = g_col[e0];
                float4 x = *(const float4*)(V + (size_t)s0 * 64 + c);
                mn.x = fminf(mn.x, x.x); mn.y = fminf(mn.y, x.y);
                mn.z = fminf(mn.z, x.z); mn.w = fminf(mn.w, x.w);
            }
            if (e1 < end) {
                int s1 = g_col[e1];
                float4 x = *(const float4*)(V + (size_t)s1 * 64 + c);
                mn.x = fminf(mn.x, x.x); mn.y = fminf(mn.y, x.y);
                mn.z = fminf(mn.z, x.z); mn.w = fminf(mn.w, x.w);
            }
        }
        mn.x = fminf(mn.x, __shfl_xor_sync(0xFFFFFFFFu, mn.x, 16));
        mn.y = fminf(mn.y, __shfl_xor_sync(0xFFFFFFFFu, mn.y, 16));
        mn.z = fminf(mn.z, __shfl_xor_sync(0xFFFFFFFFu, mn.z, 16));
        mn.w = fminf(mn.w, __shfl_xor_sync(0xFFFFFFFFu, mn.w, 16));
        if (sub == 0) {
            float4 r = make_float4(0.f, 0.f, 0.f, 0.f);
            if (end > beg) {
                float4 u = *(const float4*)(U + (size_t)node * 64 + c);
                r.x = fmaxf(u.x - mn.x, 0.f); r.y = fmaxf(u.y - mn.y, 0.f);
                r.z = fmaxf(u.z - mn.z, 0.f); r.w = fmaxf(u.w - mn.w, 0.f);
            }
            *(float4*)(out + (size_t)node * 64 + c) = r;
        }
    }
}

// Fused: H = relu(sum_j Xj@W[j] + bias) (smem only); U = H@(Wt+Wp)+bt+bp; V = H@Wt
template <int D>
__device__ void ph_fused_gemm(const float* __restrict__ X0, const float* __restrict__ X1,
                              const float* __restrict__ X2, const float* __restrict__ W,
                              const float* __restrict__ bias,
                              const float* __restrict__ Wt, const float* __restrict__ Wp,
                              const float* __restrict__ bt, const float* __restrict__ bp,
                              float* __restrict__ U, float* __restrict__ V, int n,
                              float (*XH)[68], float (*Ws)[64]) {
    const int tid = threadIdx.x;
    const int m = tid >> 2;
    const int cbase = (tid & 3) * 16;
    const int ntiles = (n + 63) >> 6;
    for (int t = blockIdx.x; t < ntiles; t += gridDim.x) {
        const int node0 = t * 64;
        const int node = node0 + m;
        float acc[16];
#pragma unroll
        for (int c = 0; c < 16; c++) acc[c] = __ldg(&bias[cbase + c]);
        const float* Xsrc[3] = {X0, X1, X2};
#pragma unroll
        for (int j = 0; j < 3; j++) {
            __syncthreads();
            const float* Xj = Xsrc[j];
            for (int i = tid; i < 64 * D; i += 256) {
                int r = i / D, c2 = i - r * D;
                int nn = node0 + r;
                XH[r][c2] = (nn < n) ? Xj[(size_t)nn * D + c2] : 0.f;
            }
            for (int i = tid; i < D * 64; i += 256) Ws[i >> 6][i & 63] = W[j * D * 64 + i];
            __syncthreads();
#pragma unroll
            for (int k = 0; k < D; k++) {
                float x = XH[m][k];
#pragma unroll
                for (int cc = 0; cc < 4; cc++) {
                    const float4 w = *(const float4*)&Ws[k][cbase + cc * 4];
                    acc[cc * 4 + 0] = fmaf(x, w.x, acc[cc * 4 + 0]);
                    acc[cc * 4 + 1] = fmaf(x, w.y, acc[cc * 4 + 1]);
                    acc[cc * 4 + 2] = fmaf(x, w.z, acc[cc * 4 + 2]);
                    acc[cc * 4 + 3] = fmaf(x, w.w, acc[cc * 4 + 3]);
                }
            }
        }
        __syncthreads();
#pragma unroll
        for (int cc = 0; cc < 4; cc++) {
            float4 h;
            h.x = fmaxf(acc[cc * 4 + 0], 0.f); h.y = fmaxf(acc[cc * 4 + 1], 0.f);
            h.z = fmaxf(acc[cc * 4 + 2], 0.f); h.w = fmaxf(acc[cc * 4 + 3], 0.f);
            *(float4*)&XH[m][cbase + cc * 4] = h;
        }
        for (int i = tid; i < 4096; i += 256) Ws[i >> 6][i & 63] = Wt[i] + Wp[i];
        __syncthreads();
#pragma unroll
        for (int c = 0; c < 16; c++) acc[c] = __ldg(&bt[cbase + c]) + __ldg(&bp[cbase + c]);
#pragma unroll
        for (int k = 0; k < 64; k++) {
            float x = XH[m][k];
#pragma unroll
            for (int cc = 0; cc < 4; cc++) {
                const float4 w = *(const float4*)&Ws[k][cbase + cc * 4];
                acc[cc * 4 + 0] = fmaf(x, w.x, acc[cc * 4 + 0]);
                acc[cc * 4 + 1] = fmaf(x, w.y, acc[cc * 4 + 1]);
                acc[cc * 4 + 2] = fmaf(x, w.z, acc[cc * 4 + 2]);
                acc[cc * 4 + 3] = fmaf(x, w.w, acc[cc * 4 + 3]);
            }
        }
        if (node < n) {
#pragma unroll
            for (int cc = 0; cc < 4; cc++)
                *(float4*)&U[(size_t)node * 64 + cbase + cc * 4] =
                    make_float4(acc[cc * 4], acc[cc * 4 + 1], acc[cc * 4 + 2], acc[cc * 4 + 3]);
        }
        __syncthreads();
        for (int i = tid; i < 4096; i += 256) Ws[i >> 6][i & 63] = Wt[i];
        __syncthreads();
#pragma unroll
        for (int c = 0; c < 16; c++) acc[c] = 0.f;
#pragma unroll
        for (int k = 0; k < 64; k++) {
            float x = XH[m][k];
#pragma unroll
            for (int cc = 0; cc < 4; cc++) {
                const float4 w = *(const float4*)&Ws[k][cbase + cc * 4];
                acc[cc * 4 + 0] = fmaf(x, w.x, acc[cc * 4 + 0]);
                acc[cc * 4 + 1] = fmaf(x, w.y, acc[cc * 4 + 1]);
                acc[cc * 4 + 2] = fmaf(x, w.z, acc[cc * 4 + 2]);
                acc[cc * 4 + 3] = fmaf(x, w.w, acc[cc * 4 + 3]);
            }
        }
        if (node < n) {
#pragma unroll
            for (int cc = 0; cc < 4; cc++)
                *(float4*)&V[(size_t)node * 64 + cbase + cc * 4] =
                    make_float4(acc[cc * 4], acc[cc * 4 + 1], acc[cc * 4 + 2], acc[cc * 4 + 3]);
        }
        __syncthreads();
    }
}

// Final Cheb layer: out = relu(X0@W0 + X1@W1 + X2@W2 + bias)
__device__ void ph_cheb_gemm(const float* __restrict__ X0, const float* __restrict__ X1,
                             const float* __restrict__ X2, const float* __restrict__ W,
                             const float* __restrict__ bias, float* __restrict__ out, int n,
                             float (*Xs)[68], float (*Ws)[64]) {
    const int tid = threadIdx.x;
    const int m = tid >> 2;
    const int cbase = (tid & 3) * 16;
    const int ntiles = (n + 63) >> 6;
    for (int t = blockIdx.x; t < ntiles; t += gridDim.x) {
        const int node0 = t * 64;
        const int node = node0 + m;
        float acc[16];
#pragma unroll
        for (int c = 0; c < 16; c++) acc[c] = __ldg(&bias[cbase + c]);
        const float* Xsrc[3] = {X0, X1, X2};
#pragma unroll
        for (int j = 0; j < 3; j++) {
            __syncthreads();
            const float* Xj = Xsrc[j];
            for (int i = tid; i < 4096; i += 256) {
                int r = i >> 6, c2 = i & 63;
                int nn = node0 + r;
                Xs[r][c2] = (nn < n) ? Xj[(size_t)nn * 64 + c2] : 0.f;
                Ws[r][c2] = W[j * 4096 + i];
            }
            __syncthreads();
#pragma unroll
            for (int k = 0; k < 64; k++) {
                float x = Xs[m][k];
#pragma unroll
                for (int cc = 0; cc < 4; cc++) {
                    const float4 w = *(const float4*)&Ws[k][cbase + cc * 4];
                    acc[cc * 4 + 0] = fmaf(x, w.x, acc[cc * 4 + 0]);
                    acc[cc * 4 + 1] = fmaf(x, w.y, acc[cc * 4 + 1]);
                    acc[cc * 4 + 2] = fmaf(x, w.z, acc[cc * 4 + 2]);
                    acc[cc * 4 + 3] = fmaf(x, w.w, acc[cc * 4 + 3]);
                }
            }
        }
        if (node < n) {
#pragma unroll
            for (int cc = 0; cc < 4; cc++) {
                float4 r;
                r.x = fmaxf(acc[cc * 4 + 0], 0.f); r.y = fmaxf(acc[cc * 4 + 1], 0.f);
                r.z = fmaxf(acc[cc * 4 + 2], 0.f); r.w = fmaxf(acc[cc * 4 + 3], 0.f);
                *(float4*)&out[(size_t)node * 64 + cbase + cc * 4] = r;
            }
        }
        __syncthreads();
    }
}

// ---------------- the single persistent kernel ----------------
__global__ void __launch_bounds__(256, 4) mega_kernel(
    const float* __restrict__ feat, const int* __restrict__ src,
    const int* __restrict__ dst, const int* __restrict__ gid,
    const float* __restrict__ W1, const float* __restrict__ b1,
    const float* __restrict__ W2, const float* __restrict__ b2,
    const float* __restrict__ W3, const float* __restrict__ b3,
    const float* __restrict__ Wt1, const float* __restrict__ bt1,
    const float* __restrict__ Wp1, const float* __restrict__ bp1,
    const float* __restrict__ Wt2, const float* __restrict__ bt2,
    const float* __restrict__ Wp2, const float* __restrict__ bp2,
    float* __restrict__ out, int n, int e, int G) {
    __shared__ __align__(16) float sA[64][68];
    __shared__ __align__(16) float sB[64][64];
    __shared__ int s_ws[9];
    __shared__ int s_run;

    const int nb = gridDim.x;
    const int tid = threadIdx.x;
    const int lane = tid & 31, wid = tid >> 5;
    const int gtid = blockIdx.x * 256 + tid;
    const int nthreads = nb * 256;
    const int gw = blockIdx.x * 8 + wid;      // global warp id
    const int nwarps = nb * 8;

    // ---- A: zero degree + pooling accumulators ----
    for (int i = gtid; i < n; i += nthreads) g_deg[i] = 0;
    for (int i = gtid; i < G * 64; i += nthreads) g_gsum[i] = 0.f;
    for (int i = gtid; i < G; i += nthreads) g_gcnt[i] = 0;
    gsync(nb);

    // ---- B: degree count ----
    for (int i = gtid; i < e; i += nthreads) atomicAdd(&g_deg[dst[i]], 1);
    gsync(nb);

    // ---- C1: per-block exclusive scan of g_deg chunk -> g_rowptr (local), block totals ----
    const int per = (n + nb - 1) / nb;
    const int rng0 = blockIdx.x * per;
    const int rng1 = min(n, rng0 + per);
    if (tid == 0) s_run = 0;
    __syncthreads();
    for (int t0 = rng0; t0 < rng1; t0 += 1024) {
        int base = t0 + tid * 4;
        int v[4]; int s = 0;
#pragma unroll
        for (int j = 0; j < 4; j++) { int i = base + j; v[j] = (i < rng1) ? g_deg[i] : 0; s += v[j]; }
        int inc = s;
#pragma unroll
        for (int o = 1; o < 32; o <<= 1) { int x = __shfl_up_sync(0xFFFFFFFFu, inc, o); if (lane >= o) inc += x; }
        if (lane == 31) s_ws[wid] = inc;
        __syncthreads();
        if (wid == 0) {
            int w = (lane < 8) ? s_ws[lane] : 0;
            int winc = w;
#pragma unroll
            for (int o = 1; o < 8; o <<= 1) { int x = __shfl_up_sync(0xFFFFFFFFu, winc, o); if (lane >= o) winc += x; }
            if (lane < 8) s_ws[lane] = winc - w;
            if (lane == 7) s_ws[8] = winc;
        }
        __syncthreads();
        int off = s_run + s_ws[wid] + (inc - s);
#pragma unroll
        for (int j = 0; j < 4; j++) { int i = base + j; if (i < rng1) { g_rowptr[i] = off; off += v[j]; } }
        __syncthreads();
        if (tid == 0) s_run += s_ws[8];
        __syncthreads();
    }
    if (tid == 0) g_bsums[blockIdx.x] = s_run;
    gsync(nb);

    // ---- C3: block 0 scans block totals (nb <= 1024) ----
    if (blockIdx.x == 0) {
        int base = tid * 4;
        int v[4]; int s = 0;
#pragma unroll
        for (int j = 0; j < 4; j++) { int i = base + j; v[j] = (i < nb) ? g_bsums[i] : 0; s += v[j]; }
        int inc = s;
#pragma unroll
        for (int o = 1; o < 32; o <<= 1) { int x = __shfl_up_sync(0xFFFFFFFFu, inc, o); if (lane >= o) inc += x; }
        if (lane == 31) s_ws[wid] = inc;
        __syncthreads();
        if (wid == 0) {
            int w = (lane < 8) ? s_ws[lane] : 0;
            int winc = w;
#pragma unroll
            for (int o = 1; o < 8; o <<= 1) { int x = __shfl_up_sync(0xFFFFFFFFu, winc, o); if (lane >= o) winc += x; }
            if (lane < 8) s_ws[lane] = winc - w;
        }
        __syncthreads();
        int off = s_ws[wid] + (inc - s);
#pragma unroll
        for (int j = 0; j < 4; j++) { int i = base + j; if (i < nb) { g_bsums[i] = off; off += v[j]; } }
    }
    gsync(nb);

    // ---- C5: add block offsets; cursor; dinv; rowptr[n] ----
    {
        int off = g_bsums[blockIdx.x];
        for (int i = rng0 + tid; i < rng1; i += 256) {
            int r = g_rowptr[i] + off;
            g_rowptr[i] = r;
            g_cursor[i] = r;
            int d = g_deg[i];
            g_dinv[i] = (d > 0) ? rsqrtf((float)d) : 1.0f;
        }
        if (gtid == 0) g_rowptr[n] = e;
    }
    gsync(nb);

    // ---- D: fill CSR ----
    for (int i = gtid; i < e; i += nthreads) {
        int d = dst[i], s = src[i];
        int p = atomicAdd(&g_cursor[d], 1);
        g_col[p] = s;
        g_ew[p] = g_dinv[s];
    }
    gsync(nb);

    // ---- Layer 1 (Cheb 16->64) ----
    ph_aggr16(feat, nullptr, g_B1, -1.f, 0.f, n, gw, nwarps);
    gsync(nb);
    ph_aggr16(g_B1, feat, g_B2, -2.f, -1.f, n, gw, nwarps);
    gsync(nb);
    // ---- Layers 1+2 GEMMs: H1 (smem) -> U=B3, V=B4 ----
    ph_fused_gemm<16>(feat, g_B1, g_B2, W1, b1, Wt1, Wp1, bt1, bp1, g_B3, g_B4, n, sA, sB);
    gsync(nb);
    ph_edge_min(g_B3, g_B4, g_B1, n, gw, nwarps);       // H2 -> B1
    gsync(nb);

    // ---- Layer 3 (Cheb 64->64) ----
    ph_aggr64(g_B1, nullptr, g_B2, -1.f, 0.f, n, gw, nwarps);
    gsync(nb);
    ph_aggr64(g_B2, g_B1, g_B3, -2.f, -1.f, n, gw, nwarps);
    gsync(nb);
    // ---- Layers 3+4 GEMMs: in-place U->B2, V->B3 (tile-local, reads precede writes) ----
    ph_fused_gemm<64>(g_B1, g_B2, g_B3, W2, b2, Wt2, Wp2, bt2, bp2, g_B2, g_B3, n, sA, sB);
    gsync(nb);
    ph_edge_min(g_B2, g_B3, g_B1, n, gw, nwarps);       // H4 -> B1
    gsync(nb);

    // ---- Layer 5 (Cheb 64->64) ----
    ph_aggr64(g_B1, nullptr, g_B2, -1.f, 0.f, n, gw, nwarps);
    gsync(nb);
    ph_aggr64(g_B2, g_B1, g_B3, -2.f, -1.f, n, gw, nwarps);
    gsync(nb);
    ph_cheb_gemm(g_B1, g_B2, g_B3, W3, b3, g_B4, n, sA, sB);
    gsync(nb);

    // ---- Pool: per-graph mean (graph_ids sorted) ----
    {
        int chunk = (n + nwarps - 1) / nwarps;
        int pbeg = gw * chunk, pend = min(n, pbeg + chunk);
        if (pbeg < pend) {
            float sx = 0.f, sy = 0.f;
            int cur = gid[pbeg]; int cnt = 0;
            for (int i = pbeg; i < pend; i++) {
                int g = gid[i];
                if (g != cur) {
                    atomicAdd(&g_gsum[cur * 64 + lane * 2], sx);
                    atomicAdd(&g_gsum[cur * 64 + lane * 2 + 1], sy);
                    if (lane == 0) atomicAdd(&g_gcnt[cur], cnt);
                    sx = 0.f; sy = 0.f; cnt = 0; cur = g;
                }
                float2 v = *(const float2*)(g_B4 + (size_t)i * 64 + lane * 2);
                sx += v.x; sy += v.y; cnt++;
            }
            atomicAdd(&g_gsum[cur * 64 + lane * 2], sx);
            atomicAdd(&g_gsum[cur * 64 + lane * 2 + 1], sy);
            if (lane == 0) atomicAdd(&g_gcnt[cur], cnt);
        }
    }
    gsync(nb);

    // ---- Finalize ----
    for (int i = gtid; i < G * 64; i += nthreads) {
        int c = g_gcnt[i >> 6];
        out[i] = g_gsum[i] / (c > 0 ? (float)c : 1.0f);
    }
}

// ---------------- launch ----------------
extern "C" void kernel_launch(void* const* d_in, const int* in_sizes, int n_in,
                              void* d_out, int out_size) {
    const float* feat = (const float*)d_in[0];
    const int*   src  = (const int*)d_in[1];
    const int*   dst  = (const int*)d_in[2];
    const int*   gid  = (const int*)d_in[3];
    const float* W1 = (const float*)d_in[4];  const float* b1 = (const float*)d_in[5];
    const float* W2 = (const float*)d_in[6];  const float* b2 = (const float*)d_in[7];
    const float* W3 = (const float*)d_in[8];  const float* b3 = (const float*)d_in[9];
    const float* Wt1 = (const float*)d_in[10]; const float* bt1 = (const float*)d_in[11];
    const float* Wp1 = (const float*)d_in[12]; const float* bp1 = (const float*)d_in[13];
    const float* Wt2 = (const float*)d_in[14]; const float* bt2 = (const float*)d_in[15];
    const float* Wp2 = (const float*)d_in[16]; const float* bp2 = (const float*)d_in[17];
    float* out = (float*)d_out;

    const int n = in_sizes[0] / 16;
    const int e = in_sizes[1];
    const int G = out_size / 64;

    int dev = 0;
    cudaGetDevice(&dev);
    int sms = 0;
    cudaDeviceGetAttribute(&sms, cudaDevAttrMultiProcessorCount, dev);
    if (sms <= 0) sms = 148;
    int perSM = 0;
    cudaOccupancyMaxActiveBlocksPerMultiprocessor(&perSM, mega_kernel, 256, 0);
    if (perSM <= 0) perSM = 1;
    int grid = sms * perSM;
    if (grid > MAXB) grid = MAXB;

    mega_kernel<<<grid, 256>>>(feat, src, dst, gid,
                               W1, b1, W2, b2, W3, b3,
                               Wt1, bt1, Wp1, bp1, Wt2, bt2, Wp2, bp2,
                               out, n, e, G);
}

// round 6
// speedup vs baseline: 14.2704x; 1.0008x over previous
#include <cuda_runtime.h>
#include <math.h>

#define MAXN 100000
#define MAXE 1600000
#define MAXG 128
#define MAXB 1024

// ---------------- scratch (static __device__ — no allocation) ----------------
__device__ int   g_deg[MAXN];
__device__ float g_dinv[MAXN];
__device__ int   g_rowptr[MAXN + 1];
__device__ int   g_cursor[MAXN];
__device__ int   g_col[MAXE];
__device__ float g_ew[MAXE];
__device__ int   g_bsums[MAXB];
__device__ float g_B1[(size_t)MAXN * 64];
__device__ float g_B2[(size_t)MAXN * 64];
__device__ float g_B3[(size_t)MAXN * 64];
__device__ float g_B4[(size_t)MAXN * 64];
__device__ float g_gsum[MAXG * 64];
__device__ int   g_gcnt[MAXG];
__device__ unsigned g_epoch;   // monotonically increasing across replays
__device__ unsigned g_cnt;

// ---------------- grid-wide barrier (all blocks co-resident by construction) ----------------
__device__ __forceinline__ void gsync(int nb) {
    __syncthreads();
    if (threadIdx.x == 0) {
        __threadfence();                       // release
        volatile unsigned* ep = &g_epoch;
        unsigned e = *ep;
        if (atomicAdd(&g_cnt, 1u) == (unsigned)(nb - 1)) {
            g_cnt = 0;
            __threadfence();
            *ep = e + 1;
        } else {
            while (*ep == e) {}
            __threadfence();                   // acquire
        }
    }
    __syncthreads();
}

// ---------------- phase helpers ----------------
// out = alpha * dinv_i * sum_e w_e * f[col_e]  (+ beta * extra_i), 64-dim rows
__device__ void ph_aggr64(const float* __restrict__ f, const float* __restrict__ extra,
                          float* __restrict__ out, float alpha, float beta,
                          int n, int gw, int nwarps) {
    const int lane = threadIdx.x & 31;
    const int sub = lane >> 4;
    const int c = (lane & 15) * 4;
    for (int node = gw; node < n; node += nwarps) {
        const int beg = g_rowptr[node], end = g_rowptr[node + 1];
        float4 acc = make_float4(0.f, 0.f, 0.f, 0.f);
        for (int e = beg; e < end; e += 4) {
            int e0 = e + sub, e1 = e + 2 + sub;
            bool v0 = e0 < end, v1 = e1 < end;
            int   s0 = v0 ? g_col[e0] : 0;
            float w0 = v0 ? g_ew[e0] : 0.f;
            int   s1 = v1 ? g_col[e1] : 0;
            float w1 = v1 ? g_ew[e1] : 0.f;
            float4 x0 = *(const float4*)(f + (size_t)s0 * 64 + c);
            float4 x1 = *(const float4*)(f + (size_t)s1 * 64 + c);
            acc.x = fmaf(w0, x0.x, acc.x); acc.y = fmaf(w0, x0.y, acc.y);
            acc.z = fmaf(w0, x0.z, acc.z); acc.w = fmaf(w0, x0.w, acc.w);
            acc.x = fmaf(w1, x1.x, acc.x); acc.y = fmaf(w1, x1.y, acc.y);
            acc.z = fmaf(w1, x1.z, acc.z); acc.w = fmaf(w1, x1.w, acc.w);
        }
        acc.x += __shfl_xor_sync(0xFFFFFFFFu, acc.x, 16);
        acc.y += __shfl_xor_sync(0xFFFFFFFFu, acc.y, 16);
        acc.z += __shfl_xor_sync(0xFFFFFFFFu, acc.z, 16);
        acc.w += __shfl_xor_sync(0xFFFFFFFFu, acc.w, 16);
        if (sub == 0) {
            float s = alpha * g_dinv[node];
            float4 r = make_float4(s * acc.x, s * acc.y, s * acc.z, s * acc.w);
            if (extra) {
                float4 ex = *(const float4*)(extra + (size_t)node * 64 + c);
                r.x = fmaf(beta, ex.x, r.x); r.y = fmaf(beta, ex.y, r.y);
                r.z = fmaf(beta, ex.z, r.z); r.w = fmaf(beta, ex.w, r.w);
            }
            *(float4*)(out + (size_t)node * 64 + c) = r;
        }
    }
}

__device__ void ph_aggr16(const float* __restrict__ f, const float* __restrict__ extra,
                          float* __restrict__ out, float alpha, float beta,
                          int n, int gw, int nwarps) {
    const int lane = threadIdx.x & 31;
    const int sub = lane >> 2;
    const int c = (lane & 3) * 4;
    for (int node = gw; node < n; node += nwarps) {
        const int beg = g_rowptr[node], end = g_rowptr[node + 1];
        float4 acc = make_float4(0.f, 0.f, 0.f, 0.f);
        for (int e = beg; e < end; e += 8) {
            int ee = e + sub;
            bool v = ee < end;
            int   s = v ? g_col[ee] : 0;
            float w = v ? g_ew[ee] : 0.f;
            float4 x = *(const float4*)(f + (size_t)s * 16 + c);
            acc.x = fmaf(w, x.x, acc.x); acc.y = fmaf(w, x.y, acc.y);
            acc.z = fmaf(w, x.z, acc.z); acc.w = fmaf(w, x.w, acc.w);
        }
#pragma unroll
        for (int o = 4; o < 32; o <<= 1) {
            acc.x += __shfl_xor_sync(0xFFFFFFFFu, acc.x, o);
            acc.y += __shfl_xor_sync(0xFFFFFFFFu, acc.y, o);
            acc.z += __shfl_xor_sync(0xFFFFFFFFu, acc.z, o);
            acc.w += __shfl_xor_sync(0xFFFFFFFFu, acc.w, o);
        }
        if (lane < 4) {
            float s = alpha * g_dinv[node];
            float4 r = make_float4(s * acc.x, s * acc.y, s * acc.z, s * acc.w);
            if (extra) {
                float4 ex = *(const float4*)(extra + (size_t)node * 16 + c);
                r.x = fmaf(beta, ex.x, r.x); r.y = fmaf(beta, ex.y, r.y);
                r.z = fmaf(beta, ex.z, r.z); r.w = fmaf(beta, ex.w, r.w);
            }
            *(float4*)(out + (size_t)node * 16 + c) = r;
        }
    }
}

// out_i = relu(U_i - min_{j->i} V_j), 0 if no in-edges
__device__ void ph_edge_min(const float* __restrict__ U, const float* __restrict__ V,
                            float* __restrict__ out, int n, int gw, int nwarps) {
    const int lane = threadIdx.x & 31;
    const int sub = lane >> 4;
    const int c = (lane & 15) * 4;
    for (int node = gw; node < n; node += nwarps) {
        const int beg = g_rowptr[node], end = g_rowptr[node + 1];
        float4 mn = make_float4(3.4e38f, 3.4e38f, 3.4e38f, 3.4e38f);
        for (int e = beg; e < end; e += 4) {
            int e0 = e + sub, e1 = e + 2 + sub;
            if (e0 < end) {
                int s0 = g_col[e0];
                float4 x = *(const float4*)(V + (size_t)s0 * 64 + c);
                mn.x = fminf(mn.x, x.x); mn.y = fminf(mn.y, x.y);
                mn.z = fminf(mn.z, x.z); mn.w = fminf(mn.w, x.w);
            }
            if (e1 < end) {
                int s1 = g_col[e1];
                float4 x = *(const float4*)(V + (size_t)s1 * 64 + c);
                mn.x = fminf(mn.x, x.x); mn.y = fminf(mn.y, x.y);
                mn.z = fminf(mn.z, x.z); mn.w = fminf(mn.w, x.w);
            }
        }
        mn.x = fminf(mn.x, __shfl_xor_sync(0xFFFFFFFFu, mn.x, 16));
        mn.y = fminf(mn.y, __shfl_xor_sync(0xFFFFFFFFu, mn.y, 16));
        mn.z = fminf(mn.z, __shfl_xor_sync(0xFFFFFFFFu, mn.z, 16));
        mn.w = fminf(mn.w, __shfl_xor_sync(0xFFFFFFFFu, mn.w, 16));
        if (sub == 0) {
            float4 r = make_float4(0.f, 0.f, 0.f, 0.f);
            if (end > beg) {
                float4 u = *(const float4*)(U + (size_t)node * 64 + c);
                r.x = fmaxf(u.x - mn.x, 0.f); r.y = fmaxf(u.y - mn.y, 0.f);
                r.z = fmaxf(u.z - mn.z, 0.f); r.w = fmaxf(u.w - mn.w, 0.f);
            }
            *(float4*)(out + (size_t)node * 64 + c) = r;
        }
    }
}

// Fused: H = relu(sum_j Xj@W[j] + bias) (smem only); U = H@(Wt+Wp)+bt+bp; V = H@Wt
template <int D>
__device__ void ph_fused_gemm(const float* __restrict__ X0, const float* __restrict__ X1,
                              const float* __restrict__ X2, const float* __restrict__ W,
                              const float* __restrict__ bias,
                              const float* __restrict__ Wt, const float* __restrict__ Wp,
                              const float* __restrict__ bt, const float* __restrict__ bp,
                              float* __restrict__ U, float* __restrict__ V, int n,
                              float (*XH)[68], float (*Ws)[64]) {
    const int tid = threadIdx.x;
    const int m = tid >> 2;
    const int cbase = (tid & 3) * 16;
    const int ntiles = (n + 63) >> 6;
    for (int t = blockIdx.x; t < ntiles; t += gridDim.x) {
        const int node0 = t * 64;
        const int node = node0 + m;
        float acc[16];
#pragma unroll
        for (int c = 0; c < 16; c++) acc[c] = __ldg(&bias[cbase + c]);
        const float* Xsrc[3] = {X0, X1, X2};
#pragma unroll
        for (int j = 0; j < 3; j++) {
            __syncthreads();
            const float* Xj = Xsrc[j];
            for (int i = tid; i < 64 * D; i += 256) {
                int r = i / D, c2 = i - r * D;
                int nn = node0 + r;
                XH[r][c2] = (nn < n) ? Xj[(size_t)nn * D + c2] : 0.f;
            }
            for (int i = tid; i < D * 64; i += 256) Ws[i >> 6][i & 63] = W[j * D * 64 + i];
            __syncthreads();
#pragma unroll
            for (int k = 0; k < D; k++) {
                float x = XH[m][k];
#pragma unroll
                for (int cc = 0; cc < 4; cc++) {
                    const float4 w = *(const float4*)&Ws[k][cbase + cc * 4];
                    acc[cc * 4 + 0] = fmaf(x, w.x, acc[cc * 4 + 0]);
                    acc[cc * 4 + 1] = fmaf(x, w.y, acc[cc * 4 + 1]);
                    acc[cc * 4 + 2] = fmaf(x, w.z, acc[cc * 4 + 2]);
                    acc[cc * 4 + 3] = fmaf(x, w.w, acc[cc * 4 + 3]);
                }
            }
        }
        __syncthreads();
#pragma unroll
        for (int cc = 0; cc < 4; cc++) {
            float4 h;
            h.x = fmaxf(acc[cc * 4 + 0], 0.f); h.y = fmaxf(acc[cc * 4 + 1], 0.f);
            h.z = fmaxf(acc[cc * 4 + 2], 0.f); h.w = fmaxf(acc[cc * 4 + 3], 0.f);
            *(float4*)&XH[m][cbase + cc * 4] = h;
        }
        for (int i = tid; i < 4096; i += 256) Ws[i >> 6][i & 63] = Wt[i] + Wp[i];
        __syncthreads();
#pragma unroll
        for (int c = 0; c < 16; c++) acc[c] = __ldg(&bt[cbase + c]) + __ldg(&bp[cbase + c]);
#pragma unroll
        for (int k = 0; k < 64; k++) {
            float x = XH[m][k];
#pragma unroll
            for (int cc = 0; cc < 4; cc++) {
                const float4 w = *(const float4*)&Ws[k][cbase + cc * 4];
                acc[cc * 4 + 0] = fmaf(x, w.x, acc[cc * 4 + 0]);
                acc[cc * 4 + 1] = fmaf(x, w.y, acc[cc * 4 + 1]);
                acc[cc * 4 + 2] = fmaf(x, w.z, acc[cc * 4 + 2]);
                acc[cc * 4 + 3] = fmaf(x, w.w, acc[cc * 4 + 3]);
            }
        }
        if (node < n) {
#pragma unroll
            for (int cc = 0; cc < 4; cc++)
                *(float4*)&U[(size_t)node * 64 + cbase + cc * 4] =
                    make_float4(acc[cc * 4], acc[cc * 4 + 1], acc[cc * 4 + 2], acc[cc * 4 + 3]);
        }
        __syncthreads();
        for (int i = tid; i < 4096; i += 256) Ws[i >> 6][i & 63] = Wt[i];
        __syncthreads();
#pragma unroll
        for (int c = 0; c < 16; c++) acc[c] = 0.f;
#pragma unroll
        for (int k = 0; k < 64; k++) {
            float x = XH[m][k];
#pragma unroll
            for (int cc = 0; cc < 4; cc++) {
                const float4 w = *(const float4*)&Ws[k][cbase + cc * 4];
                acc[cc * 4 + 0] = fmaf(x, w.x, acc[cc * 4 + 0]);
                acc[cc * 4 + 1] = fmaf(x, w.y, acc[cc * 4 + 1]);
                acc[cc * 4 + 2] = fmaf(x, w.z, acc[cc * 4 + 2]);
                acc[cc * 4 + 3] = fmaf(x, w.w, acc[cc * 4 + 3]);
            }
        }
        if (node < n) {
#pragma unroll
            for (int cc = 0; cc < 4; cc++)
                *(float4*)&V[(size_t)node * 64 + cbase + cc * 4] =
                    make_float4(acc[cc * 4], acc[cc * 4 + 1], acc[cc * 4 + 2], acc[cc * 4 + 3]);
        }
        __syncthreads();
    }
}

// Final Cheb layer: out = relu(X0@W0 + X1@W1 + X2@W2 + bias)
__device__ void ph_cheb_gemm(const float* __restrict__ X0, const float* __restrict__ X1,
                             const float* __restrict__ X2, const float* __restrict__ W,
                             const float* __restrict__ bias, float* __restrict__ out, int n,
                             float (*Xs)[68], float (*Ws)[64]) {
    const int tid = threadIdx.x;
    const int m = tid >> 2;
    const int cbase = (tid & 3) * 16;
    const int ntiles = (n + 63) >> 6;
    for (int t = blockIdx.x; t < ntiles; t += gridDim.x) {
        const int node0 = t * 64;
        const int node = node0 + m;
        float acc[16];
#pragma unroll
        for (int c = 0; c < 16; c++) acc[c] = __ldg(&bias[cbase + c]);
        const float* Xsrc[3] = {X0, X1, X2};
#pragma unroll
        for (int j = 0; j < 3; j++) {
            __syncthreads();
            const float* Xj = Xsrc[j];
            for (int i = tid; i < 4096; i += 256) {
                int r = i >> 6, c2 = i & 63;
                int nn = node0 + r;
                Xs[r][c2] = (nn < n) ? Xj[(size_t)nn * 64 + c2] : 0.f;
                Ws[r][c2] = W[j * 4096 + i];
            }
            __syncthreads();
#pragma unroll
            for (int k = 0; k < 64; k++) {
                float x = Xs[m][k];
#pragma unroll
                for (int cc = 0; cc < 4; cc++) {
                    const float4 w = *(const float4*)&Ws[k][cbase + cc * 4];
                    acc[cc * 4 + 0] = fmaf(x, w.x, acc[cc * 4 + 0]);
                    acc[cc * 4 + 1] = fmaf(x, w.y, acc[cc * 4 + 1]);
                    acc[cc * 4 + 2] = fmaf(x, w.z, acc[cc * 4 + 2]);
                    acc[cc * 4 + 3] = fmaf(x, w.w, acc[cc * 4 + 3]);
                }
            }
        }
        if (node < n) {
#pragma unroll
            for (int cc = 0; cc < 4; cc++) {
                float4 r;
                r.x = fmaxf(acc[cc * 4 + 0], 0.f); r.y = fmaxf(acc[cc * 4 + 1], 0.f);
                r.z = fmaxf(acc[cc * 4 + 2], 0.f); r.w = fmaxf(acc[cc * 4 + 3], 0.f);
                *(float4*)&out[(size_t)node * 64 + cbase + cc * 4] = r;
            }
        }
        __syncthreads();
    }
}

// ---------------- the single persistent kernel ----------------
__global__ void __launch_bounds__(256, 4) mega_kernel(
    const float* __restrict__ feat, const int* __restrict__ src,
    const int* __restrict__ dst, const int* __restrict__ gid,
    const float* __restrict__ W1, const float* __restrict__ b1,
    const float* __restrict__ W2, const float* __restrict__ b2,
    const float* __restrict__ W3, const float* __restrict__ b3,
    const float* __restrict__ Wt1, const float* __restrict__ bt1,
    const float* __restrict__ Wp1, const float* __restrict__ bp1,
    const float* __restrict__ Wt2, const float* __restrict__ bt2,
    const float* __restrict__ Wp2, const float* __restrict__ bp2,
    float* __restrict__ out, int n, int e, int G) {
    __shared__ __align__(16) float sA[64][68];
    __shared__ __align__(16) float sB[64][64];
    __shared__ int s_ws[9];
    __shared__ int s_run;

    const int nb = gridDim.x;
    const int tid = threadIdx.x;
    const int lane = tid & 31, wid = tid >> 5;
    const int gtid = blockIdx.x * 256 + tid;
    const int nthreads = nb * 256;
    const int gw = blockIdx.x * 8 + wid;      // global warp id
    const int nwarps = nb * 8;

    // ---- A: zero degree + pooling accumulators ----
    for (int i = gtid; i < n; i += nthreads) g_deg[i] = 0;
    for (int i = gtid; i < G * 64; i += nthreads) g_gsum[i] = 0.f;
    for (int i = gtid; i < G; i += nthreads) g_gcnt[i] = 0;
    gsync(nb);

    // ---- B: degree count ----
    for (int i = gtid; i < e; i += nthreads) atomicAdd(&g_deg[dst[i]], 1);
    gsync(nb);

    // ---- C1: per-block exclusive scan of g_deg chunk -> g_rowptr (local), block totals ----
    const int per = (n + nb - 1) / nb;
    const int rng0 = blockIdx.x * per;
    const int rng1 = min(n, rng0 + per);
    if (tid == 0) s_run = 0;
    __syncthreads();
    for (int t0 = rng0; t0 < rng1; t0 += 1024) {
        int base = t0 + tid * 4;
        int v[4]; int s = 0;
#pragma unroll
        for (int j = 0; j < 4; j++) { int i = base + j; v[j] = (i < rng1) ? g_deg[i] : 0; s += v[j]; }
        int inc = s;
#pragma unroll
        for (int o = 1; o < 32; o <<= 1) { int x = __shfl_up_sync(0xFFFFFFFFu, inc, o); if (lane >= o) inc += x; }
        if (lane == 31) s_ws[wid] = inc;
        __syncthreads();
        if (wid == 0) {
            int w = (lane < 8) ? s_ws[lane] : 0;
            int winc = w;
#pragma unroll
            for (int o = 1; o < 8; o <<= 1) { int x = __shfl_up_sync(0xFFFFFFFFu, winc, o); if (lane >= o) winc += x; }
            if (lane < 8) s_ws[lane] = winc - w;
            if (lane == 7) s_ws[8] = winc;
        }
        __syncthreads();
        int off = s_run + s_ws[wid] + (inc - s);
#pragma unroll
        for (int j = 0; j < 4; j++) { int i = base + j; if (i < rng1) { g_rowptr[i] = off; off += v[j]; } }
        __syncthreads();
        if (tid == 0) s_run += s_ws[8];
        __syncthreads();
    }
    if (tid == 0) g_bsums[blockIdx.x] = s_run;
    gsync(nb);

    // ---- C3: block 0 scans block totals (nb <= 1024) ----
    if (blockIdx.x == 0) {
        int base = tid * 4;
        int v[4]; int s = 0;
#pragma unroll
        for (int j = 0; j < 4; j++) { int i = base + j; v[j] = (i < nb) ? g_bsums[i] : 0; s += v[j]; }
        int inc = s;
#pragma unroll
        for (int o = 1; o < 32; o <<= 1) { int x = __shfl_up_sync(0xFFFFFFFFu, inc, o); if (lane >= o) inc += x; }
        if (lane == 31) s_ws[wid] = inc;
        __syncthreads();
        if (wid == 0) {
            int w = (lane < 8) ? s_ws[lane] : 0;
            int winc = w;
#pragma unroll
            for (int o = 1; o < 8; o <<= 1) { int x = __shfl_up_sync(0xFFFFFFFFu, winc, o); if (lane >= o) winc += x; }
            if (lane < 8) s_ws[lane] = winc - w;
        }
        __syncthreads();
        int off = s_ws[wid] + (inc - s);
#pragma unroll
        for (int j = 0; j < 4; j++) { int i = base + j; if (i < nb) { g_bsums[i] = off; off += v[j]; } }
    }
    gsync(nb);

    // ---- C5: add block offsets; cursor; dinv; rowptr[n] ----
    {
        int off = g_bsums[blockIdx.x];
        for (int i = rng0 + tid; i < rng1; i += 256) {
            int r = g_rowptr[i] + off;
            g_rowptr[i] = r;
            g_cursor[i] = r;
            int d = g_deg[i];
            g_dinv[i] = (d > 0) ? rsqrtf((float)d) : 1.0f;
        }
        if (gtid == 0) g_rowptr[n] = e;
    }
    gsync(nb);

    // ---- D: fill CSR ----
    for (int i = gtid; i < e; i += nthreads) {
        int d = dst[i], s = src[i];
        int p = atomicAdd(&g_cursor[d], 1);
        g_col[p] = s;
        g_ew[p] = g_dinv[s];
    }
    gsync(nb);

    // ---- Layer 1 (Cheb 16->64) ----
    ph_aggr16(feat, nullptr, g_B1, -1.f, 0.f, n, gw, nwarps);
    gsync(nb);
    ph_aggr16(g_B1, feat, g_B2, -2.f, -1.f, n, gw, nwarps);
    gsync(nb);
    // ---- Layers 1+2 GEMMs: H1 (smem) -> U=B3, V=B4 ----
    ph_fused_gemm<16>(feat, g_B1, g_B2, W1, b1, Wt1, Wp1, bt1, bp1, g_B3, g_B4, n, sA, sB);
    gsync(nb);
    ph_edge_min(g_B3, g_B4, g_B1, n, gw, nwarps);       // H2 -> B1
    gsync(nb);

    // ---- Layer 3 (Cheb 64->64) ----
    ph_aggr64(g_B1, nullptr, g_B2, -1.f, 0.f, n, gw, nwarps);
    gsync(nb);
    ph_aggr64(g_B2, g_B1, g_B3, -2.f, -1.f, n, gw, nwarps);
    gsync(nb);
    // ---- Layers 3+4 GEMMs: in-place U->B2, V->B3 (tile-local, reads precede writes) ----
    ph_fused_gemm<64>(g_B1, g_B2, g_B3, W2, b2, Wt2, Wp2, bt2, bp2, g_B2, g_B3, n, sA, sB);
    gsync(nb);
    ph_edge_min(g_B2, g_B3, g_B1, n, gw, nwarps);       // H4 -> B1
    gsync(nb);

    // ---- Layer 5 (Cheb 64->64) ----
    ph_aggr64(g_B1, nullptr, g_B2, -1.f, 0.f, n, gw, nwarps);
    gsync(nb);
    ph_aggr64(g_B2, g_B1, g_B3, -2.f, -1.f, n, gw, nwarps);
    gsync(nb);
    ph_cheb_gemm(g_B1, g_B2, g_B3, W3, b3, g_B4, n, sA, sB);
    gsync(nb);

    // ---- Pool: per-graph mean (graph_ids sorted) ----
    {
        int chunk = (n + nwarps - 1) / nwarps;
        int pbeg = gw * chunk, pend = min(n, pbeg + chunk);
        if (pbeg < pend) {
            float sx = 0.f, sy = 0.f;
            int cur = gid[pbeg]; int cnt = 0;
            for (int i = pbeg; i < pend; i++) {
                int g = gid[i];
                if (g != cur) {
                    atomicAdd(&g_gsum[cur * 64 + lane * 2], sx);
                    atomicAdd(&g_gsum[cur * 64 + lane * 2 + 1], sy);
                    if (lane == 0) atomicAdd(&g_gcnt[cur], cnt);
                    sx = 0.f; sy = 0.f; cnt = 0; cur = g;
                }
                float2 v = *(const float2*)(g_B4 + (size_t)i * 64 + lane * 2);
                sx += v.x; sy += v.y; cnt++;
            }
            atomicAdd(&g_gsum[cur * 64 + lane * 2], sx);
            atomicAdd(&g_gsum[cur * 64 + lane * 2 + 1], sy);
            if (lane == 0) atomicAdd(&g_gcnt[cur], cnt);
        }
    }
    gsync(nb);

    // ---- Finalize ----
    for (int i = gtid; i < G * 64; i += nthreads) {
        int c = g_gcnt[i >> 6];
        out[i] = g_gsum[i] / (c > 0 ? (float)c : 1.0f);
    }
}

// ---------------- launch ----------------
extern "C" void kernel_launch(void* const* d_in, const int* in_sizes, int n_in,
                              void* d_out, int out_size) {
    const float* feat = (const float*)d_in[0];
    const int*   src  = (const int*)d_in[1];
    const int*   dst  = (const int*)d_in[2];
    const int*   gid  = (const int*)d_in[3];
    const float* W1 = (const float*)d_in[4];  const float* b1 = (const float*)d_in[5];
    const float* W2 = (const float*)d_in[6];  const float* b2 = (const float*)d_in[7];
    const float* W3 = (const float*)d_in[8];  const float* b3 = (const float*)d_in[9];
    const float* Wt1 = (const float*)d_in[10]; const float* bt1 = (const float*)d_in[11];
    const float* Wp1 = (const float*)d_in[12]; const float* bp1 = (const float*)d_in[13];
    const float* Wt2 = (const float*)d_in[14]; const float* bt2 = (const float*)d_in[15];
    const float* Wp2 = (const float*)d_in[16]; const float* bp2 = (const float*)d_in[17];
    float* out = (float*)d_out;

    const int n = in_sizes[0] / 16;
    const int e = in_sizes[1];
    const int G = out_size / 64;

    int dev = 0;
    cudaGetDevice(&dev);
    int sms = 0;
    cudaDeviceGetAttribute(&sms, cudaDevAttrMultiProcessorCount, dev);
    if (sms <= 0) sms = 148;
    int perSM = 0;
    cudaOccupancyMaxActiveBlocksPerMultiprocessor(&perSM, mega_kernel, 256, 0);
    if (perSM <= 0) perSM = 1;
    int grid = sms * perSM;
    if (grid > MAXB) grid = MAXB;

    mega_kernel<<<grid, 256>>>(feat, src, dst, gid,
                               W1, b1, W2, b2, W3, b3,
                               Wt1, bt1, Wp1, bp1, Wt2, bt2, Wp2, bp2,
                               out, n, e, G);
}

// round 7
// speedup vs baseline: 14.3820x; 1.0078x over previous
#include <cuda_runtime.h>
#include <math.h>

#define MAXN 100000
#define MAXE 1600000
#define MAXG 128
#define MAXB 1024

// ---------------- scratch (static __device__ — zero-initialized at load) ----------------
__device__ int   g_deg[MAXN];          // zeroed by finalize of previous replay (and at load)
__device__ float g_dinv[MAXN];
__device__ int   g_rowptr[MAXN + 1];
__device__ int   g_cursor[MAXN];
__device__ int   g_col[MAXE];
__device__ float g_ew[MAXE];
__device__ int   g_bsums[MAXB];
__device__ float g_B1[(size_t)MAXN * 64];
__device__ float g_B2[(size_t)MAXN * 64];
__device__ float g_B3[(size_t)MAXN * 64];
__device__ float g_B4[(size_t)MAXN * 64];
__device__ float g_gsum[MAXG * 64];
__device__ int   g_gcnt[MAXG];
__device__ unsigned g_epoch;   // monotonically increasing across replays
__device__ unsigned g_cnt;

// ---------------- grid-wide barrier (all blocks co-resident by construction) ----------------
__device__ __forceinline__ void gsync(int nb) {
    __syncthreads();
    if (threadIdx.x == 0) {
        __threadfence();                       // release
        volatile unsigned* ep = &g_epoch;
        unsigned e = *ep;
        if (atomicAdd(&g_cnt, 1u) == (unsigned)(nb - 1)) {
            g_cnt = 0;
            __threadfence();
            *ep = e + 1;
        } else {
            while (*ep == e) {}
            __threadfence();                   // acquire
        }
    }
    __syncthreads();
}

// ---------------- phase helpers ----------------
// out = alpha * dinv_i * sum_e w_e * f[col_e]  (+ beta * extra_i), 64-dim rows
// 16 lanes x float4 per row; 4 edge-slots in flight (MLP 4)
__device__ void ph_aggr64(const float* __restrict__ f, const float* __restrict__ extra,
                          float* __restrict__ out, float alpha, float beta,
                          int n, int gw, int nwarps) {
    const int lane = threadIdx.x & 31;
    const int sub = lane >> 4;
    const int c = (lane & 15) * 4;
    for (int node = gw; node < n; node += nwarps) {
        const int beg = g_rowptr[node], end = g_rowptr[node + 1];
        float4 acc = make_float4(0.f, 0.f, 0.f, 0.f);
        for (int e = beg; e < end; e += 8) {
            int ea = e + sub, eb = e + 2 + sub, ec = e + 4 + sub, ed = e + 6 + sub;
            bool va = ea < end, vb = eb < end, vc = ec < end, vd = ed < end;
            int   sa = va ? g_col[ea] : 0;  float wa = va ? g_ew[ea] : 0.f;
            int   sb = vb ? g_col[eb] : 0;  float wb = vb ? g_ew[eb] : 0.f;
            int   sc = vc ? g_col[ec] : 0;  float wc = vc ? g_ew[ec] : 0.f;
            int   sd = vd ? g_col[ed] : 0;  float wd = vd ? g_ew[ed] : 0.f;
            float4 xa = *(const float4*)(f + (size_t)sa * 64 + c);
            float4 xb = *(const float4*)(f + (size_t)sb * 64 + c);
            float4 xc = *(const float4*)(f + (size_t)sc * 64 + c);
            float4 xd = *(const float4*)(f + (size_t)sd * 64 + c);
            acc.x = fmaf(wa, xa.x, acc.x); acc.y = fmaf(wa, xa.y, acc.y);
            acc.z = fmaf(wa, xa.z, acc.z); acc.w = fmaf(wa, xa.w, acc.w);
            acc.x = fmaf(wb, xb.x, acc.x); acc.y = fmaf(wb, xb.y, acc.y);
            acc.z = fmaf(wb, xb.z, acc.z); acc.w = fmaf(wb, xb.w, acc.w);
            acc.x = fmaf(wc, xc.x, acc.x); acc.y = fmaf(wc, xc.y, acc.y);
            acc.z = fmaf(wc, xc.z, acc.z); acc.w = fmaf(wc, xc.w, acc.w);
            acc.x = fmaf(wd, xd.x, acc.x); acc.y = fmaf(wd, xd.y, acc.y);
            acc.z = fmaf(wd, xd.z, acc.z); acc.w = fmaf(wd, xd.w, acc.w);
        }
        acc.x += __shfl_xor_sync(0xFFFFFFFFu, acc.x, 16);
        acc.y += __shfl_xor_sync(0xFFFFFFFFu, acc.y, 16);
        acc.z += __shfl_xor_sync(0xFFFFFFFFu, acc.z, 16);
        acc.w += __shfl_xor_sync(0xFFFFFFFFu, acc.w, 16);
        if (sub == 0) {
            float s = alpha * g_dinv[node];
            float4 r = make_float4(s * acc.x, s * acc.y, s * acc.z, s * acc.w);
            if (extra) {
                float4 ex = *(const float4*)(extra + (size_t)node * 64 + c);
                r.x = fmaf(beta, ex.x, r.x); r.y = fmaf(beta, ex.y, r.y);
                r.z = fmaf(beta, ex.z, r.z); r.w = fmaf(beta, ex.w, r.w);
            }
            *(float4*)(out + (size_t)node * 64 + c) = r;
        }
    }
}

__device__ void ph_aggr16(const float* __restrict__ f, const float* __restrict__ extra,
                          float* __restrict__ out, float alpha, float beta,
                          int n, int gw, int nwarps) {
    const int lane = threadIdx.x & 31;
    const int sub = lane >> 2;
    const int c = (lane & 3) * 4;
    for (int node = gw; node < n; node += nwarps) {
        const int beg = g_rowptr[node], end = g_rowptr[node + 1];
        float4 acc = make_float4(0.f, 0.f, 0.f, 0.f);
        for (int e = beg; e < end; e += 16) {
            int e0 = e + sub, e1 = e + 8 + sub;
            bool v0 = e0 < end, v1 = e1 < end;
            int   s0 = v0 ? g_col[e0] : 0;  float w0 = v0 ? g_ew[e0] : 0.f;
            int   s1 = v1 ? g_col[e1] : 0;  float w1 = v1 ? g_ew[e1] : 0.f;
            float4 x0 = *(const float4*)(f + (size_t)s0 * 16 + c);
            float4 x1 = *(const float4*)(f + (size_t)s1 * 16 + c);
            acc.x = fmaf(w0, x0.x, acc.x); acc.y = fmaf(w0, x0.y, acc.y);
            acc.z = fmaf(w0, x0.z, acc.z); acc.w = fmaf(w0, x0.w, acc.w);
            acc.x = fmaf(w1, x1.x, acc.x); acc.y = fmaf(w1, x1.y, acc.y);
            acc.z = fmaf(w1, x1.z, acc.z); acc.w = fmaf(w1, x1.w, acc.w);
        }
#pragma unroll
        for (int o = 4; o < 32; o <<= 1) {
            acc.x += __shfl_xor_sync(0xFFFFFFFFu, acc.x, o);
            acc.y += __shfl_xor_sync(0xFFFFFFFFu, acc.y, o);
            acc.z += __shfl_xor_sync(0xFFFFFFFFu, acc.z, o);
            acc.w += __shfl_xor_sync(0xFFFFFFFFu, acc.w, o);
        }
        if (lane < 4) {
            float s = alpha * g_dinv[node];
            float4 r = make_float4(s * acc.x, s * acc.y, s * acc.z, s * acc.w);
            if (extra) {
                float4 ex = *(const float4*)(extra + (size_t)node * 16 + c);
                r.x = fmaf(beta, ex.x, r.x); r.y = fmaf(beta, ex.y, r.y);
                r.z = fmaf(beta, ex.z, r.z); r.w = fmaf(beta, ex.w, r.w);
            }
            *(float4*)(out + (size_t)node * 16 + c) = r;
        }
    }
}

// out_i = relu(U_i - min_{j->i} V_j), 0 if no in-edges; 4 edge-slots in flight
__device__ void ph_edge_min(const float* __restrict__ U, const float* __restrict__ V,
                            float* __restrict__ out, int n, int gw, int nwarps) {
    const int lane = threadIdx.x & 31;
    const int sub = lane >> 4;
    const int c = (lane & 15) * 4;
    const float INF = 3.4e38f;
    for (int node = gw; node < n; node += nwarps) {
        const int beg = g_rowptr[node], end = g_rowptr[node + 1];
        float4 mn = make_float4(INF, INF, INF, INF);
        for (int e = beg; e < end; e += 8) {
            int ea = e + sub, eb = e + 2 + sub, ec = e + 4 + sub, ed = e + 6 + sub;
            bool va = ea < end, vb = eb < end, vc = ec < end, vd = ed < end;
            int sa = va ? g_col[ea] : 0;
            int sb = vb ? g_col[eb] : 0;
            int sc = vc ? g_col[ec] : 0;
            int sd = vd ? g_col[ed] : 0;
            float4 xa = *(const float4*)(V + (size_t)sa * 64 + c);
            float4 xb = *(const float4*)(V + (size_t)sb * 64 + c);
            float4 xc = *(const float4*)(V + (size_t)sc * 64 + c);
            float4 xd = *(const float4*)(V + (size_t)sd * 64 + c);
            if (va) { mn.x = fminf(mn.x, xa.x); mn.y = fminf(mn.y, xa.y);
                      mn.z = fminf(mn.z, xa.z); mn.w = fminf(mn.w, xa.w); }
            if (vb) { mn.x = fminf(mn.x, xb.x); mn.y = fminf(mn.y, xb.y);
                      mn.z = fminf(mn.z, xb.z); mn.w = fminf(mn.w, xb.w); }
            if (vc) { mn.x = fminf(mn.x, xc.x); mn.y = fminf(mn.y, xc.y);
                      mn.z = fminf(mn.z, xc.z); mn.w = fminf(mn.w, xc.w); }
            if (vd) { mn.x = fminf(mn.x, xd.x); mn.y = fminf(mn.y, xd.y);
                      mn.z = fminf(mn.z, xd.z); mn.w = fminf(mn.w, xd.w); }
        }
        mn.x = fminf(mn.x, __shfl_xor_sync(0xFFFFFFFFu, mn.x, 16));
        mn.y = fminf(mn.y, __shfl_xor_sync(0xFFFFFFFFu, mn.y, 16));
        mn.z = fminf(mn.z, __shfl_xor_sync(0xFFFFFFFFu, mn.z, 16));
        mn.w = fminf(mn.w, __shfl_xor_sync(0xFFFFFFFFu, mn.w, 16));
        if (sub == 0) {
            float4 r = make_float4(0.f, 0.f, 0.f, 0.f);
            if (end > beg) {
                float4 u = *(const float4*)(U + (size_t)node * 64 + c);
                r.x = fmaxf(u.x - mn.x, 0.f); r.y = fmaxf(u.y - mn.y, 0.f);
                r.z = fmaxf(u.z - mn.z, 0.f); r.w = fmaxf(u.w - mn.w, 0.f);
            }
            *(float4*)(out + (size_t)node * 64 + c) = r;
        }
    }
}

// Fused: H = relu(sum_j Xj@W[j] + bias) (smem only); U = H@(Wt+Wp)+bt+bp; V = H@Wt
template <int D>
__device__ void ph_fused_gemm(const float* __restrict__ X0, const float* __restrict__ X1,
                              const float* __restrict__ X2, const float* __restrict__ W,
                              const float* __restrict__ bias,
                              const float* __restrict__ Wt, const float* __restrict__ Wp,
                              const float* __restrict__ bt, const float* __restrict__ bp,
                              float* __restrict__ U, float* __restrict__ V, int n,
                              float (*XH)[68], float (*Ws)[64]) {
    const int tid = threadIdx.x;
    const int m = tid >> 2;
    const int cbase = (tid & 3) * 16;
    const int ntiles = (n + 63) >> 6;
    for (int t = blockIdx.x; t < ntiles; t += gridDim.x) {
        const int node0 = t * 64;
        const int node = node0 + m;
        float acc[16];
#pragma unroll
        for (int c = 0; c < 16; c++) acc[c] = __ldg(&bias[cbase + c]);
        const float* Xsrc[3] = {X0, X1, X2};
#pragma unroll
        for (int j = 0; j < 3; j++) {
            __syncthreads();
            const float* Xj = Xsrc[j];
            for (int i = tid; i < 64 * D; i += 256) {
                int r = i / D, c2 = i - r * D;
                int nn = node0 + r;
                XH[r][c2] = (nn < n) ? Xj[(size_t)nn * D + c2] : 0.f;
            }
            for (int i = tid; i < D * 64; i += 256) Ws[i >> 6][i & 63] = W[j * D * 64 + i];
            __syncthreads();
#pragma unroll
            for (int k = 0; k < D; k++) {
                float x = XH[m][k];
#pragma unroll
                for (int cc = 0; cc < 4; cc++) {
                    const float4 w = *(const float4*)&Ws[k][cbase + cc * 4];
                    acc[cc * 4 + 0] = fmaf(x, w.x, acc[cc * 4 + 0]);
                    acc[cc * 4 + 1] = fmaf(x, w.y, acc[cc * 4 + 1]);
                    acc[cc * 4 + 2] = fmaf(x, w.z, acc[cc * 4 + 2]);
                    acc[cc * 4 + 3] = fmaf(x, w.w, acc[cc * 4 + 3]);
                }
            }
        }
        __syncthreads();
#pragma unroll
        for (int cc = 0; cc < 4; cc++) {
            float4 h;
            h.x = fmaxf(acc[cc * 4 + 0], 0.f); h.y = fmaxf(acc[cc * 4 + 1], 0.f);
            h.z = fmaxf(acc[cc * 4 + 2], 0.f); h.w = fmaxf(acc[cc * 4 + 3], 0.f);
            *(float4*)&XH[m][cbase + cc * 4] = h;
        }
        for (int i = tid; i < 4096; i += 256) Ws[i >> 6][i & 63] = Wt[i] + Wp[i];
        __syncthreads();
#pragma unroll
        for (int c = 0; c < 16; c++) acc[c] = __ldg(&bt[cbase + c]) + __ldg(&bp[cbase + c]);
#pragma unroll
        for (int k = 0; k < 64; k++) {
            float x = XH[m][k];
#pragma unroll
            for (int cc = 0; cc < 4; cc++) {
                const float4 w = *(const float4*)&Ws[k][cbase + cc * 4];
                acc[cc * 4 + 0] = fmaf(x, w.x, acc[cc * 4 + 0]);
                acc[cc * 4 + 1] = fmaf(x, w.y, acc[cc * 4 + 1]);
                acc[cc * 4 + 2] = fmaf(x, w.z, acc[cc * 4 + 2]);
                acc[cc * 4 + 3] = fmaf(x, w.w, acc[cc * 4 + 3]);
            }
        }
        if (node < n) {
#pragma unroll
            for (int cc = 0; cc < 4; cc++)
                *(float4*)&U[(size_t)node * 64 + cbase + cc * 4] =
                    make_float4(acc[cc * 4], acc[cc * 4 + 1], acc[cc * 4 + 2], acc[cc * 4 + 3]);
        }
        __syncthreads();
        for (int i = tid; i < 4096; i += 256) Ws[i >> 6][i & 63] = Wt[i];
        __syncthreads();
#pragma unroll
        for (int c = 0; c < 16; c++) acc[c] = 0.f;
#pragma unroll
        for (int k = 0; k < 64; k++) {
            float x = XH[m][k];
#pragma unroll
            for (int cc = 0; cc < 4; cc++) {
                const float4 w = *(const float4*)&Ws[k][cbase + cc * 4];
                acc[cc * 4 + 0] = fmaf(x, w.x, acc[cc * 4 + 0]);
                acc[cc * 4 + 1] = fmaf(x, w.y, acc[cc * 4 + 1]);
                acc[cc * 4 + 2] = fmaf(x, w.z, acc[cc * 4 + 2]);
                acc[cc * 4 + 3] = fmaf(x, w.w, acc[cc * 4 + 3]);
            }
        }
        if (node < n) {
#pragma unroll
            for (int cc = 0; cc < 4; cc++)
                *(float4*)&V[(size_t)node * 64 + cbase + cc * 4] =
                    make_float4(acc[cc * 4], acc[cc * 4 + 1], acc[cc * 4 + 2], acc[cc * 4 + 3]);
        }
        __syncthreads();
    }
}

// Final Cheb layer: out = relu(X0@W0 + X1@W1 + X2@W2 + bias)
__device__ void ph_cheb_gemm(const float* __restrict__ X0, const float* __restrict__ X1,
                             const float* __restrict__ X2, const float* __restrict__ W,
                             const float* __restrict__ bias, float* __restrict__ out, int n,
                             float (*Xs)[68], float (*Ws)[64]) {
    const int tid = threadIdx.x;
    const int m = tid >> 2;
    const int cbase = (tid & 3) * 16;
    const int ntiles = (n + 63) >> 6;
    for (int t = blockIdx.x; t < ntiles; t += gridDim.x) {
        const int node0 = t * 64;
        const int node = node0 + m;
        float acc[16];
#pragma unroll
        for (int c = 0; c < 16; c++) acc[c] = __ldg(&bias[cbase + c]);
        const float* Xsrc[3] = {X0, X1, X2};
#pragma unroll
        for (int j = 0; j < 3; j++) {
            __syncthreads();
            const float* Xj = Xsrc[j];
            for (int i = tid; i < 4096; i += 256) {
                int r = i >> 6, c2 = i & 63;
                int nn = node0 + r;
                Xs[r][c2] = (nn < n) ? Xj[(size_t)nn * 64 + c2] : 0.f;
                Ws[r][c2] = W[j * 4096 + i];
            }
            __syncthreads();
#pragma unroll
            for (int k = 0; k < 64; k++) {
                float x = Xs[m][k];
#pragma unroll
                for (int cc = 0; cc < 4; cc++) {
                    const float4 w = *(const float4*)&Ws[k][cbase + cc * 4];
                    acc[cc * 4 + 0] = fmaf(x, w.x, acc[cc * 4 + 0]);
                    acc[cc * 4 + 1] = fmaf(x, w.y, acc[cc * 4 + 1]);
                    acc[cc * 4 + 2] = fmaf(x, w.z, acc[cc * 4 + 2]);
                    acc[cc * 4 + 3] = fmaf(x, w.w, acc[cc * 4 + 3]);
                }
            }
        }
        if (node < n) {
#pragma unroll
            for (int cc = 0; cc < 4; cc++) {
                float4 r;
                r.x = fmaxf(acc[cc * 4 + 0], 0.f); r.y = fmaxf(acc[cc * 4 + 1], 0.f);
                r.z = fmaxf(acc[cc * 4 + 2], 0.f); r.w = fmaxf(acc[cc * 4 + 3], 0.f);
                *(float4*)&out[(size_t)node * 64 + cbase + cc * 4] = r;
            }
        }
        __syncthreads();
    }
}

// ---------------- the single persistent kernel ----------------
__global__ void __launch_bounds__(256, 4) mega_kernel(
    const float* __restrict__ feat, const int* __restrict__ src,
    const int* __restrict__ dst, const int* __restrict__ gid,
    const float* __restrict__ W1, const float* __restrict__ b1,
    const float* __restrict__ W2, const float* __restrict__ b2,
    const float* __restrict__ W3, const float* __restrict__ b3,
    const float* __restrict__ Wt1, const float* __restrict__ bt1,
    const float* __restrict__ Wp1, const float* __restrict__ bp1,
    const float* __restrict__ Wt2, const float* __restrict__ bt2,
    const float* __restrict__ Wp2, const float* __restrict__ bp2,
    float* __restrict__ out, int n, int e, int G) {
    __shared__ __align__(16) float sA[64][68];
    __shared__ __align__(16) float sB[64][64];
    __shared__ int s_ws[9];
    __shared__ int s_run;

    const int nb = gridDim.x;
    const int tid = threadIdx.x;
    const int lane = tid & 31, wid = tid >> 5;
    const int gtid = blockIdx.x * 256 + tid;
    const int nthreads = nb * 256;
    const int gw = blockIdx.x * 8 + wid;      // global warp id
    const int nwarps = nb * 8;

    // ---- B: degree count (g_deg zeroed by previous replay's finalize / load-time init) ----
    for (int i = gtid; i < e; i += nthreads) atomicAdd(&g_deg[dst[i]], 1);
    gsync(nb);

    // ---- C1: per-block exclusive scan of g_deg chunk -> g_rowptr (local), block totals.
    //      Also zero pooling accumulators (used much later; barriers in between). ----
    for (int i = gtid; i < G * 64; i += nthreads) g_gsum[i] = 0.f;
    for (int i = gtid; i < G; i += nthreads) g_gcnt[i] = 0;
    const int per = (n + nb - 1) / nb;
    const int rng0 = blockIdx.x * per;
    const int rng1 = min(n, rng0 + per);
    if (tid == 0) s_run = 0;
    __syncthreads();
    for (int t0 = rng0; t0 < rng1; t0 += 1024) {
        int base = t0 + tid * 4;
        int v[4]; int s = 0;
#pragma unroll
        for (int j = 0; j < 4; j++) { int i = base + j; v[j] = (i < rng1) ? g_deg[i] : 0; s += v[j]; }
        int inc = s;
#pragma unroll
        for (int o = 1; o < 32; o <<= 1) { int x = __shfl_up_sync(0xFFFFFFFFu, inc, o); if (lane >= o) inc += x; }
        if (lane == 31) s_ws[wid] = inc;
        __syncthreads();
        if (wid == 0) {
            int w = (lane < 8) ? s_ws[lane] : 0;
            int winc = w;
#pragma unroll
            for (int o = 1; o < 8; o <<= 1) { int x = __shfl_up_sync(0xFFFFFFFFu, winc, o); if (lane >= o) winc += x; }
            if (lane < 8) s_ws[lane] = winc - w;
            if (lane == 7) s_ws[8] = winc;
        }
        __syncthreads();
        int off = s_run + s_ws[wid] + (inc - s);
#pragma unroll
        for (int j = 0; j < 4; j++) { int i = base + j; if (i < rng1) { g_rowptr[i] = off; off += v[j]; } }
        __syncthreads();
        if (tid == 0) s_run += s_ws[8];
        __syncthreads();
    }
    if (tid == 0) g_bsums[blockIdx.x] = s_run;
    gsync(nb);

    // ---- C3: block 0 scans block totals (nb <= 1024) ----
    if (blockIdx.x == 0) {
        int base = tid * 4;
        int v[4]; int s = 0;
#pragma unroll
        for (int j = 0; j < 4; j++) { int i = base + j; v[j] = (i < nb) ? g_bsums[i] : 0; s += v[j]; }
        int inc = s;
#pragma unroll
        for (int o = 1; o < 32; o <<= 1) { int x = __shfl_up_sync(0xFFFFFFFFu, inc, o); if (lane >= o) inc += x; }
        if (lane == 31) s_ws[wid] = inc;
        __syncthreads();
        if (wid == 0) {
            int w = (lane < 8) ? s_ws[lane] : 0;
            int winc = w;
#pragma unroll
            for (int o = 1; o < 8; o <<= 1) { int x = __shfl_up_sync(0xFFFFFFFFu, winc, o); if (lane >= o) winc += x; }
            if (lane < 8) s_ws[lane] = winc - w;
        }
        __syncthreads();
        int off = s_ws[wid] + (inc - s);
#pragma unroll
        for (int j = 0; j < 4; j++) { int i = base + j; if (i < nb) { g_bsums[i] = off; off += v[j]; } }
    }
    gsync(nb);

    // ---- C5: add block offsets; cursor; dinv; rowptr[n] ----
    {
        int off = g_bsums[blockIdx.x];
        for (int i = rng0 + tid; i < rng1; i += 256) {
            int r = g_rowptr[i] + off;
            g_rowptr[i] = r;
            g_cursor[i] = r;
            int d = g_deg[i];
            g_dinv[i] = (d > 0) ? rsqrtf((float)d) : 1.0f;
        }
        if (gtid == 0) g_rowptr[n] = e;
    }
    gsync(nb);

    // ---- D: fill CSR ----
    for (int i = gtid; i < e; i += nthreads) {
        int d = dst[i], s = src[i];
        int p = atomicAdd(&g_cursor[d], 1);
        g_col[p] = s;
        g_ew[p] = g_dinv[s];
    }
    gsync(nb);

    // ---- Layer 1 (Cheb 16->64) ----
    ph_aggr16(feat, nullptr, g_B1, -1.f, 0.f, n, gw, nwarps);
    gsync(nb);
    ph_aggr16(g_B1, feat, g_B2, -2.f, -1.f, n, gw, nwarps);
    gsync(nb);
    // ---- Layers 1+2 GEMMs: H1 (smem) -> U=B3, V=B4 ----
    ph_fused_gemm<16>(feat, g_B1, g_B2, W1, b1, Wt1, Wp1, bt1, bp1, g_B3, g_B4, n, sA, sB);
    gsync(nb);
    ph_edge_min(g_B3, g_B4, g_B1, n, gw, nwarps);       // H2 -> B1
    gsync(nb);

    // ---- Layer 3 (Cheb 64->64) ----
    ph_aggr64(g_B1, nullptr, g_B2, -1.f, 0.f, n, gw, nwarps);
    gsync(nb);
    ph_aggr64(g_B2, g_B1, g_B3, -2.f, -1.f, n, gw, nwarps);
    gsync(nb);
    // ---- Layers 3+4 GEMMs: in-place U->B2, V->B3 (tile-local, reads precede writes) ----
    ph_fused_gemm<64>(g_B1, g_B2, g_B3, W2, b2, Wt2, Wp2, bt2, bp2, g_B2, g_B3, n, sA, sB);
    gsync(nb);
    ph_edge_min(g_B2, g_B3, g_B1, n, gw, nwarps);       // H4 -> B1
    gsync(nb);

    // ---- Layer 5 (Cheb 64->64) ----
    ph_aggr64(g_B1, nullptr, g_B2, -1.f, 0.f, n, gw, nwarps);
    gsync(nb);
    ph_aggr64(g_B2, g_B1, g_B3, -2.f, -1.f, n, gw, nwarps);
    gsync(nb);
    ph_cheb_gemm(g_B1, g_B2, g_B3, W3, b3, g_B4, n, sA, sB);
    gsync(nb);

    // ---- Pool: per-graph mean (graph_ids sorted) ----
    {
        int chunk = (n + nwarps - 1) / nwarps;
        int pbeg = gw * chunk, pend = min(n, pbeg + chunk);
        if (pbeg < pend) {
            float sx = 0.f, sy = 0.f;
            int cur = gid[pbeg]; int cnt = 0;
            for (int i = pbeg; i < pend; i++) {
                int g = gid[i];
                if (g != cur) {
                    atomicAdd(&g_gsum[cur * 64 + lane * 2], sx);
                    atomicAdd(&g_gsum[cur * 64 + lane * 2 + 1], sy);
                    if (lane == 0) atomicAdd(&g_gcnt[cur], cnt);
                    sx = 0.f; sy = 0.f; cnt = 0; cur = g;
                }
                float2 v = *(const float2*)(g_B4 + (size_t)i * 64 + lane * 2);
                sx += v.x; sy += v.y; cnt++;
            }
            atomicAdd(&g_gsum[cur * 64 + lane * 2], sx);
            atomicAdd(&g_gsum[cur * 64 + lane * 2 + 1], sy);
            if (lane == 0) atomicAdd(&g_gcnt[cur], cnt);
        }
    }
    gsync(nb);

    // ---- Finalize: write output + reset g_deg for next replay ----
    for (int i = gtid; i < G * 64; i += nthreads) {
        int c = g_gcnt[i >> 6];
        out[i] = g_gsum[i] / (c > 0 ? (float)c : 1.0f);
    }
    for (int i = gtid; i < n; i += nthreads) g_deg[i] = 0;
}

// ---------------- launch ----------------
extern "C" void kernel_launch(void* const* d_in, const int* in_sizes, int n_in,
                              void* d_out, int out_size) {
    const float* feat = (const float*)d_in[0];
    const int*   src  = (const int*)d_in[1];
    const int*   dst  = (const int*)d_in[2];
    const int*   gid  = (const int*)d_in[3];
    const float* W1 = (const float*)d_in[4];  const float* b1 = (const float*)d_in[5];
    const float* W2 = (const float*)d_in[6];  const float* b2 = (const float*)d_in[7];
    const float* W3 = (const float*)d_in[8];  const float* b3 = (const float*)d_in[9];
    const float* Wt1 = (const float*)d_in[10]; const float* bt1 = (const float*)d_in[11];
    const float* Wp1 = (const float*)d_in[12]; const float* bp1 = (const float*)d_in[13];
    const float* Wt2 = (const float*)d_in[14]; const float* bt2 = (const float*)d_in[15];
    const float* Wp2 = (const float*)d_in[16]; const float* bp2 = (const float*)d_in[17];
    float* out = (float*)d_out;

    const int n = in_sizes[0] / 16;
    const int e = in_sizes[1];
    const int G = out_size / 64;

    int dev = 0;
    cudaGetDevice(&dev);
    int sms = 0;
    cudaDeviceGetAttribute(&sms, cudaDevAttrMultiProcessorCount, dev);
    if (sms <= 0) sms = 148;
    int perSM = 0;
    cudaOccupancyMaxActiveBlocksPerMultiprocessor(&perSM, mega_kernel, 256, 0);
    if (perSM <= 0) perSM = 1;
    int grid = sms * perSM;
    if (grid > MAXB) grid = MAXB;

    mega_kernel<<<grid, 256>>>(feat, src, dst, gid,
                               W1, b1, W2, b2, W3, b3,
                               Wt1, bt1, Wp1, bp1, Wt2, bt2, Wp2, bp2,
                               out, n, e, G);
}

// round 8
// speedup vs baseline: 14.5239x; 1.0099x over previous
#include <cuda_runtime.h>
#include <math.h>

#define MAXN 100000
#define MAXE 1600000
#define MAXG 128
#define MAXB 1024

// ---------------- scratch (static __device__ — zero-initialized at load) ----------------
__device__ int   g_deg[MAXN];          // zeroed by finalize of previous replay (and at load)
__device__ float g_dinv[MAXN];
__device__ int   g_rowptr[MAXN + 1];
__device__ int   g_cursor[MAXN];
__device__ int   g_col[MAXE];
__device__ float g_ew[MAXE];
__device__ int   g_bsums[MAXB];
__device__ float g_B1[(size_t)MAXN * 64];
__device__ float g_B2[(size_t)MAXN * 64];
__device__ float g_B3[(size_t)MAXN * 64];
__device__ float g_B4[(size_t)MAXN * 64];
__device__ float g_gsum[MAXG * 64];
__device__ int   g_gcnt[MAXG];
__device__ unsigned g_epoch;   // monotonically increasing across replays
__device__ unsigned g_cnt;

// ---------------- packed f32x2 helpers (FFMA2 — PTX-only on sm_103a) ----------------
__device__ __forceinline__ void ffma2(unsigned long long& acc, unsigned long long w,
                                      unsigned long long x) {
    asm("fma.rn.f32x2 %0, %1, %2, %3;" : "=l"(acc) : "l"(w), "l"(x), "l"(acc));
}
__device__ __forceinline__ unsigned long long pack2(float a, float b) {
    unsigned long long r;
    asm("mov.b64 %0, {%1, %2};" : "=l"(r) : "f"(a), "f"(b));
    return r;
}
__device__ __forceinline__ float2 unpack2(unsigned long long r) {
    float2 f;
    asm("mov.b64 {%0, %1}, %2;" : "=f"(f.x), "=f"(f.y) : "l"(r));
    return f;
}

// ---------------- grid-wide barrier (all blocks co-resident by construction) ----------------
__device__ __forceinline__ void gsync(int nb) {
    __syncthreads();
    if (threadIdx.x == 0) {
        __threadfence();                       // release
        volatile unsigned* ep = &g_epoch;
        unsigned e = *ep;
        if (atomicAdd(&g_cnt, 1u) == (unsigned)(nb - 1)) {
            g_cnt = 0;
            __threadfence();
            *ep = e + 1;
        } else {
            while (*ep == e) {}
            __threadfence();                   // acquire
        }
    }
    __syncthreads();
}

// ---------------- phase helpers ----------------
// out = alpha * dinv_i * sum_e w_e * f[col_e]  (+ beta * extra_i), 64-dim rows
__device__ void ph_aggr64(const float* __restrict__ f, const float* __restrict__ extra,
                          float* __restrict__ out, float alpha, float beta,
                          int n, int gw, int nwarps) {
    const int lane = threadIdx.x & 31;
    const int sub = lane >> 4;
    const int c = (lane & 15) * 4;
    for (int node = gw; node < n; node += nwarps) {
        const int beg = g_rowptr[node], end = g_rowptr[node + 1];
        float4 acc = make_float4(0.f, 0.f, 0.f, 0.f);
        for (int e = beg; e < end; e += 8) {
            int ea = e + sub, eb = e + 2 + sub, ec = e + 4 + sub, ed = e + 6 + sub;
            bool va = ea < end, vb = eb < end, vc = ec < end, vd = ed < end;
            int   sa = va ? g_col[ea] : 0;  float wa = va ? g_ew[ea] : 0.f;
            int   sb = vb ? g_col[eb] : 0;  float wb = vb ? g_ew[eb] : 0.f;
            int   sc = vc ? g_col[ec] : 0;  float wc = vc ? g_ew[ec] : 0.f;
            int   sd = vd ? g_col[ed] : 0;  float wd = vd ? g_ew[ed] : 0.f;
            float4 xa = *(const float4*)(f + (size_t)sa * 64 + c);
            float4 xb = *(const float4*)(f + (size_t)sb * 64 + c);
            float4 xc = *(const float4*)(f + (size_t)sc * 64 + c);
            float4 xd = *(const float4*)(f + (size_t)sd * 64 + c);
            acc.x = fmaf(wa, xa.x, acc.x); acc.y = fmaf(wa, xa.y, acc.y);
            acc.z = fmaf(wa, xa.z, acc.z); acc.w = fmaf(wa, xa.w, acc.w);
            acc.x = fmaf(wb, xb.x, acc.x); acc.y = fmaf(wb, xb.y, acc.y);
            acc.z = fmaf(wb, xb.z, acc.z); acc.w = fmaf(wb, xb.w, acc.w);
            acc.x = fmaf(wc, xc.x, acc.x); acc.y = fmaf(wc, xc.y, acc.y);
            acc.z = fmaf(wc, xc.z, acc.z); acc.w = fmaf(wc, xc.w, acc.w);
            acc.x = fmaf(wd, xd.x, acc.x); acc.y = fmaf(wd, xd.y, acc.y);
            acc.z = fmaf(wd, xd.z, acc.z); acc.w = fmaf(wd, xd.w, acc.w);
        }
        acc.x += __shfl_xor_sync(0xFFFFFFFFu, acc.x, 16);
        acc.y += __shfl_xor_sync(0xFFFFFFFFu, acc.y, 16);
        acc.z += __shfl_xor_sync(0xFFFFFFFFu, acc.z, 16);
        acc.w += __shfl_xor_sync(0xFFFFFFFFu, acc.w, 16);
        if (sub == 0) {
            float s = alpha * g_dinv[node];
            float4 r = make_float4(s * acc.x, s * acc.y, s * acc.z, s * acc.w);
            if (extra) {
                float4 ex = *(const float4*)(extra + (size_t)node * 64 + c);
                r.x = fmaf(beta, ex.x, r.x); r.y = fmaf(beta, ex.y, r.y);
                r.z = fmaf(beta, ex.z, r.z); r.w = fmaf(beta, ex.w, r.w);
            }
            *(float4*)(out + (size_t)node * 64 + c) = r;
        }
    }
}

__device__ void ph_aggr16(const float* __restrict__ f, const float* __restrict__ extra,
                          float* __restrict__ out, float alpha, float beta,
                          int n, int gw, int nwarps) {
    const int lane = threadIdx.x & 31;
    const int sub = lane >> 2;
    const int c = (lane & 3) * 4;
    for (int node = gw; node < n; node += nwarps) {
        const int beg = g_rowptr[node], end = g_rowptr[node + 1];
        float4 acc = make_float4(0.f, 0.f, 0.f, 0.f);
        for (int e = beg; e < end; e += 16) {
            int e0 = e + sub, e1 = e + 8 + sub;
            bool v0 = e0 < end, v1 = e1 < end;
            int   s0 = v0 ? g_col[e0] : 0;  float w0 = v0 ? g_ew[e0] : 0.f;
            int   s1 = v1 ? g_col[e1] : 0;  float w1 = v1 ? g_ew[e1] : 0.f;
            float4 x0 = *(const float4*)(f + (size_t)s0 * 16 + c);
            float4 x1 = *(const float4*)(f + (size_t)s1 * 16 + c);
            acc.x = fmaf(w0, x0.x, acc.x); acc.y = fmaf(w0, x0.y, acc.y);
            acc.z = fmaf(w0, x0.z, acc.z); acc.w = fmaf(w0, x0.w, acc.w);
            acc.x = fmaf(w1, x1.x, acc.x); acc.y = fmaf(w1, x1.y, acc.y);
            acc.z = fmaf(w1, x1.z, acc.z); acc.w = fmaf(w1, x1.w, acc.w);
        }
#pragma unroll
        for (int o = 4; o < 32; o <<= 1) {
            acc.x += __shfl_xor_sync(0xFFFFFFFFu, acc.x, o);
            acc.y += __shfl_xor_sync(0xFFFFFFFFu, acc.y, o);
            acc.z += __shfl_xor_sync(0xFFFFFFFFu, acc.z, o);
            acc.w += __shfl_xor_sync(0xFFFFFFFFu, acc.w, o);
        }
        if (lane < 4) {
            float s = alpha * g_dinv[node];
            float4 r = make_float4(s * acc.x, s * acc.y, s * acc.z, s * acc.w);
            if (extra) {
                float4 ex = *(const float4*)(extra + (size_t)node * 16 + c);
                r.x = fmaf(beta, ex.x, r.x); r.y = fmaf(beta, ex.y, r.y);
                r.z = fmaf(beta, ex.z, r.z); r.w = fmaf(beta, ex.w, r.w);
            }
            *(float4*)(out + (size_t)node * 16 + c) = r;
        }
    }
}

// out_i = relu(U_i - min_{j->i} V_j), 0 if no in-edges
__device__ void ph_edge_min(const float* __restrict__ U, const float* __restrict__ V,
                            float* __restrict__ out, int n, int gw, int nwarps) {
    const int lane = threadIdx.x & 31;
    const int sub = lane >> 4;
    const int c = (lane & 15) * 4;
    const float INF = 3.4e38f;
    for (int node = gw; node < n; node += nwarps) {
        const int beg = g_rowptr[node], end = g_rowptr[node + 1];
        float4 mn = make_float4(INF, INF, INF, INF);
        for (int e = beg; e < end; e += 8) {
            int ea = e + sub, eb = e + 2 + sub, ec = e + 4 + sub, ed = e + 6 + sub;
            bool va = ea < end, vb = eb < end, vc = ec < end, vd = ed < end;
            int sa = va ? g_col[ea] : 0;
            int sb = vb ? g_col[eb] : 0;
            int sc = vc ? g_col[ec] : 0;
            int sd = vd ? g_col[ed] : 0;
            float4 xa = *(const float4*)(V + (size_t)sa * 64 + c);
            float4 xb = *(const float4*)(V + (size_t)sb * 64 + c);
            float4 xc = *(const float4*)(V + (size_t)sc * 64 + c);
            float4 xd = *(const float4*)(V + (size_t)sd * 64 + c);
            if (va) { mn.x = fminf(mn.x, xa.x); mn.y = fminf(mn.y, xa.y);
                      mn.z = fminf(mn.z, xa.z); mn.w = fminf(mn.w, xa.w); }
            if (vb) { mn.x = fminf(mn.x, xb.x); mn.y = fminf(mn.y, xb.y);
                      mn.z = fminf(mn.z, xb.z); mn.w = fminf(mn.w, xb.w); }
            if (vc) { mn.x = fminf(mn.x, xc.x); mn.y = fminf(mn.y, xc.y);
                      mn.z = fminf(mn.z, xc.z); mn.w = fminf(mn.w, xc.w); }
            if (vd) { mn.x = fminf(mn.x, xd.x); mn.y = fminf(mn.y, xd.y);
                      mn.z = fminf(mn.z, xd.z); mn.w = fminf(mn.w, xd.w); }
        }
        mn.x = fminf(mn.x, __shfl_xor_sync(0xFFFFFFFFu, mn.x, 16));
        mn.y = fminf(mn.y, __shfl_xor_sync(0xFFFFFFFFu, mn.y, 16));
        mn.z = fminf(mn.z, __shfl_xor_sync(0xFFFFFFFFu, mn.z, 16));
        mn.w = fminf(mn.w, __shfl_xor_sync(0xFFFFFFFFu, mn.w, 16));
        if (sub == 0) {
            float4 r = make_float4(0.f, 0.f, 0.f, 0.f);
            if (end > beg) {
                float4 u = *(const float4*)(U + (size_t)node * 64 + c);
                r.x = fmaxf(u.x - mn.x, 0.f); r.y = fmaxf(u.y - mn.y, 0.f);
                r.z = fmaxf(u.z - mn.z, 0.f); r.w = fmaxf(u.w - mn.w, 0.f);
            }
            *(float4*)(out + (size_t)node * 64 + c) = r;
        }
    }
}

// packed-FMA inner sweep: acc[0..7] (f32x2 pairs) += Ws[k][cbase..cbase+15] * x
__device__ __forceinline__ void gemm_sweep_k(unsigned long long* acc, const float (*Ws)[64],
                                             const float* xcol, int D, int cbase) {
    for (int k = 0; k < D; k++) {
        unsigned long long xx = pack2(xcol[k], xcol[k]);
        const ulonglong2* wrow = (const ulonglong2*)&Ws[k][cbase];
        ulonglong2 wA = wrow[0], wB = wrow[1], wC = wrow[2], wD = wrow[3];
        ffma2(acc[0], wA.x, xx); ffma2(acc[1], wA.y, xx);
        ffma2(acc[2], wB.x, xx); ffma2(acc[3], wB.y, xx);
        ffma2(acc[4], wC.x, xx); ffma2(acc[5], wC.y, xx);
        ffma2(acc[6], wD.x, xx); ffma2(acc[7], wD.y, xx);
    }
}

// Fused: H = relu(sum_j Xj@W[j] + bias) (smem only); U = H@(Wt+Wp)+bt+bp; V = H@Wt
template <int D>
__device__ void ph_fused_gemm(const float* __restrict__ X0, const float* __restrict__ X1,
                              const float* __restrict__ X2, const float* __restrict__ W,
                              const float* __restrict__ bias,
                              const float* __restrict__ Wt, const float* __restrict__ Wp,
                              const float* __restrict__ bt, const float* __restrict__ bp,
                              float* __restrict__ U, float* __restrict__ V, int n,
                              float (*XH)[68], float (*Ws)[64]) {
    const int tid = threadIdx.x;
    const int m = tid >> 2;
    const int cbase = (tid & 3) * 16;
    const int ntiles = (n + 63) >> 6;
    for (int t = blockIdx.x; t < ntiles; t += gridDim.x) {
        const int node0 = t * 64;
        const int node = node0 + m;
        unsigned long long acc[8];
#pragma unroll
        for (int p = 0; p < 8; p++) acc[p] = pack2(__ldg(&bias[cbase + 2 * p]),
                                                   __ldg(&bias[cbase + 2 * p + 1]));
        const float* Xsrc[3] = {X0, X1, X2};
#pragma unroll
        for (int j = 0; j < 3; j++) {
            __syncthreads();
            const float* Xj = Xsrc[j];
            for (int i = tid; i < 64 * D; i += 256) {
                int r = i / D, c2 = i - r * D;
                int nn = node0 + r;
                XH[r][c2] = (nn < n) ? Xj[(size_t)nn * D + c2] : 0.f;
            }
            for (int i = tid; i < D * 64; i += 256) Ws[i >> 6][i & 63] = W[j * D * 64 + i];
            __syncthreads();
            gemm_sweep_k(acc, (const float (*)[64])Ws, &XH[m][0], D, cbase);
        }
        __syncthreads();
        // relu -> H tile in smem
#pragma unroll
        for (int p = 0; p < 8; p += 2) {
            float2 a = unpack2(acc[p]), b2 = unpack2(acc[p + 1]);
            float4 h;
            h.x = fmaxf(a.x, 0.f); h.y = fmaxf(a.y, 0.f);
            h.z = fmaxf(b2.x, 0.f); h.w = fmaxf(b2.y, 0.f);
            *(float4*)&XH[m][cbase + p * 2] = h;
        }
        for (int i = tid; i < 4096; i += 256) Ws[i >> 6][i & 63] = Wt[i] + Wp[i];
        __syncthreads();
#pragma unroll
        for (int p = 0; p < 8; p++)
            acc[p] = pack2(__ldg(&bt[cbase + 2 * p]) + __ldg(&bp[cbase + 2 * p]),
                           __ldg(&bt[cbase + 2 * p + 1]) + __ldg(&bp[cbase + 2 * p + 1]));
        gemm_sweep_k(acc, (const float (*)[64])Ws, &XH[m][0], 64, cbase);
        if (node < n) {
#pragma unroll
            for (int p = 0; p < 8; p += 2) {
                float2 a = unpack2(acc[p]), b2 = unpack2(acc[p + 1]);
                *(float4*)&U[(size_t)node * 64 + cbase + p * 2] = make_float4(a.x, a.y, b2.x, b2.y);
            }
        }
        __syncthreads();
        for (int i = tid; i < 4096; i += 256) Ws[i >> 6][i & 63] = Wt[i];
        __syncthreads();
#pragma unroll
        for (int p = 0; p < 8; p++) acc[p] = 0ull;   // two packed 0.0f
        gemm_sweep_k(acc, (const float (*)[64])Ws, &XH[m][0], 64, cbase);
        if (node < n) {
#pragma unroll
            for (int p = 0; p < 8; p += 2) {
                float2 a = unpack2(acc[p]), b2 = unpack2(acc[p + 1]);
                *(float4*)&V[(size_t)node * 64 + cbase + p * 2] = make_float4(a.x, a.y, b2.x, b2.y);
            }
        }
        __syncthreads();
    }
}

// Final Cheb layer: out = relu(X0@W0 + X1@W1 + X2@W2 + bias)
__device__ void ph_cheb_gemm(const float* __restrict__ X0, const float* __restrict__ X1,
                             const float* __restrict__ X2, const float* __restrict__ W,
                             const float* __restrict__ bias, float* __restrict__ out, int n,
                             float (*Xs)[68], float (*Ws)[64]) {
    const int tid = threadIdx.x;
    const int m = tid >> 2;
    const int cbase = (tid & 3) * 16;
    const int ntiles = (n + 63) >> 6;
    for (int t = blockIdx.x; t < ntiles; t += gridDim.x) {
        const int node0 = t * 64;
        const int node = node0 + m;
        unsigned long long acc[8];
#pragma unroll
        for (int p = 0; p < 8; p++) acc[p] = pack2(__ldg(&bias[cbase + 2 * p]),
                                                   __ldg(&bias[cbase + 2 * p + 1]));
        const float* Xsrc[3] = {X0, X1, X2};
#pragma unroll
        for (int j = 0; j < 3; j++) {
            __syncthreads();
            const float* Xj = Xsrc[j];
            for (int i = tid; i < 4096; i += 256) {
                int r = i >> 6, c2 = i & 63;
                int nn = node0 + r;
                Xs[r][c2] = (nn < n) ? Xj[(size_t)nn * 64 + c2] : 0.f;
                Ws[r][c2] = W[j * 4096 + i];
            }
            __syncthreads();
            gemm_sweep_k(acc, (const float (*)[64])Ws, &Xs[m][0], 64, cbase);
        }
        if (node < n) {
#pragma unroll
            for (int p = 0; p < 8; p += 2) {
                float2 a = unpack2(acc[p]), b2 = unpack2(acc[p + 1]);
                float4 r;
                r.x = fmaxf(a.x, 0.f); r.y = fmaxf(a.y, 0.f);
                r.z = fmaxf(b2.x, 0.f); r.w = fmaxf(b2.y, 0.f);
                *(float4*)&out[(size_t)node * 64 + cbase + p * 2] = r;
            }
        }
        __syncthreads();
    }
}

// ---------------- the single persistent kernel ----------------
__global__ void __launch_bounds__(256, 4) mega_kernel(
    const float* __restrict__ feat, const int* __restrict__ src,
    const int* __restrict__ dst, const int* __restrict__ gid,
    const float* __restrict__ W1, const float* __restrict__ b1,
    const float* __restrict__ W2, const float* __restrict__ b2,
    const float* __restrict__ W3, const float* __restrict__ b3,
    const float* __restrict__ Wt1, const float* __restrict__ bt1,
    const float* __restrict__ Wp1, const float* __restrict__ bp1,
    const float* __restrict__ Wt2, const float* __restrict__ bt2,
    const float* __restrict__ Wp2, const float* __restrict__ bp2,
    float* __restrict__ out, int n, int e, int G) {
    __shared__ __align__(16) float sA[64][68];
    __shared__ __align__(16) float sB[64][64];
    __shared__ int s_ws[9];
    __shared__ int s_run;

    const int nb = gridDim.x;
    const int tid = threadIdx.x;
    const int lane = tid & 31, wid = tid >> 5;
    const int gtid = blockIdx.x * 256 + tid;
    const int nthreads = nb * 256;
    const int gw = blockIdx.x * 8 + wid;      // global warp id
    const int nwarps = nb * 8;

    // ---- B: degree count (g_deg zeroed by previous replay's finalize / load-time init) ----
    for (int i = gtid; i < e; i += nthreads) atomicAdd(&g_deg[dst[i]], 1);
    gsync(nb);

    // ---- C1: per-block exclusive scan of g_deg chunk; zero pooling accumulators ----
    for (int i = gtid; i < G * 64; i += nthreads) g_gsum[i] = 0.f;
    for (int i = gtid; i < G; i += nthreads) g_gcnt[i] = 0;
    const int per = (n + nb - 1) / nb;
    const int rng0 = blockIdx.x * per;
    const int rng1 = min(n, rng0 + per);
    if (tid == 0) s_run = 0;
    __syncthreads();
    for (int t0 = rng0; t0 < rng1; t0 += 1024) {
        int base = t0 + tid * 4;
        int v[4]; int s = 0;
#pragma unroll
        for (int j = 0; j < 4; j++) { int i = base + j; v[j] = (i < rng1) ? g_deg[i] : 0; s += v[j]; }
        int inc = s;
#pragma unroll
        for (int o = 1; o < 32; o <<= 1) { int x = __shfl_up_sync(0xFFFFFFFFu, inc, o); if (lane >= o) inc += x; }
        if (lane == 31) s_ws[wid] = inc;
        __syncthreads();
        if (wid == 0) {
            int w = (lane < 8) ? s_ws[lane] : 0;
            int winc = w;
#pragma unroll
            for (int o = 1; o < 8; o <<= 1) { int x = __shfl_up_sync(0xFFFFFFFFu, winc, o); if (lane >= o) winc += x; }
            if (lane < 8) s_ws[lane] = winc - w;
            if (lane == 7) s_ws[8] = winc;
        }
        __syncthreads();
        int off = s_run + s_ws[wid] + (inc - s);
#pragma unroll
        for (int j = 0; j < 4; j++) { int i = base + j; if (i < rng1) { g_rowptr[i] = off; off += v[j]; } }
        __syncthreads();
        if (tid == 0) s_run += s_ws[8];
        __syncthreads();
    }
    if (tid == 0) g_bsums[blockIdx.x] = s_run;
    gsync(nb);

    // ---- C3: block 0 scans block totals (nb <= 1024) ----
    if (blockIdx.x == 0) {
        int base = tid * 4;
        int v[4]; int s = 0;
#pragma unroll
        for (int j = 0; j < 4; j++) { int i = base + j; v[j] = (i < nb) ? g_bsums[i] : 0; s += v[j]; }
        int inc = s;
#pragma unroll
        for (int o = 1; o < 32; o <<= 1) { int x = __shfl_up_sync(0xFFFFFFFFu, inc, o); if (lane >= o) inc += x; }
        if (lane == 31) s_ws[wid] = inc;
        __syncthreads();
        if (wid == 0) {
            int w = (lane < 8) ? s_ws[lane] : 0;
            int winc = w;
#pragma unroll
            for (int o = 1; o < 8; o <<= 1) { int x = __shfl_up_sync(0xFFFFFFFFu, winc, o); if (lane >= o) winc += x; }
            if (lane < 8) s_ws[lane] = winc - w;
        }
        __syncthreads();
        int off = s_ws[wid] + (inc - s);
#pragma unroll
        for (int j = 0; j < 4; j++) { int i = base + j; if (i < nb) { g_bsums[i] = off; off += v[j]; } }
    }
    gsync(nb);

    // ---- C5: add block offsets; cursor; dinv; rowptr[n] ----
    {
        int off = g_bsums[blockIdx.x];
        for (int i = rng0 + tid; i < rng1; i += 256) {
            int r = g_rowptr[i] + off;
            g_rowptr[i] = r;
            g_cursor[i] = r;
            int d = g_deg[i];
            g_dinv[i] = (d > 0) ? rsqrtf((float)d) : 1.0f;
        }
        if (gtid == 0) g_rowptr[n] = e;
    }
    gsync(nb);

    // ---- D: fill CSR ----
    for (int i = gtid; i < e; i += nthreads) {
        int d = dst[i], s = src[i];
        int p = atomicAdd(&g_cursor[d], 1);
        g_col[p] = s;
        g_ew[p] = g_dinv[s];
    }
    gsync(nb);

    // ---- Layer 1 (Cheb 16->64) ----
    ph_aggr16(feat, nullptr, g_B1, -1.f, 0.f, n, gw, nwarps);
    gsync(nb);
    ph_aggr16(g_B1, feat, g_B2, -2.f, -1.f, n, gw, nwarps);
    gsync(nb);
    // ---- Layers 1+2 GEMMs: H1 (smem) -> U=B3, V=B4 ----
    ph_fused_gemm<16>(feat, g_B1, g_B2, W1, b1, Wt1, Wp1, bt1, bp1, g_B3, g_B4, n, sA, sB);
    gsync(nb);
    ph_edge_min(g_B3, g_B4, g_B1, n, gw, nwarps);       // H2 -> B1
    gsync(nb);

    // ---- Layer 3 (Cheb 64->64) ----
    ph_aggr64(g_B1, nullptr, g_B2, -1.f, 0.f, n, gw, nwarps);
    gsync(nb);
    ph_aggr64(g_B2, g_B1, g_B3, -2.f, -1.f, n, gw, nwarps);
    gsync(nb);
    // ---- Layers 3+4 GEMMs: in-place U->B2, V->B3 (tile-local, reads precede writes) ----
    ph_fused_gemm<64>(g_B1, g_B2, g_B3, W2, b2, Wt2, Wp2, bt2, bp2, g_B2, g_B3, n, sA, sB);
    gsync(nb);
    ph_edge_min(g_B2, g_B3, g_B1, n, gw, nwarps);       // H4 -> B1
    gsync(nb);

    // ---- Layer 5 (Cheb 64->64) ----
    ph_aggr64(g_B1, nullptr, g_B2, -1.f, 0.f, n, gw, nwarps);
    gsync(nb);
    ph_aggr64(g_B2, g_B1, g_B3, -2.f, -1.f, n, gw, nwarps);
    gsync(nb);
    ph_cheb_gemm(g_B1, g_B2, g_B3, W3, b3, g_B4, n, sA, sB);
    gsync(nb);

    // ---- Pool: per-graph mean (graph_ids sorted) ----
    {
        int chunk = (n + nwarps - 1) / nwarps;
        int pbeg = gw * chunk, pend = min(n, pbeg + chunk);
        if (pbeg < pend) {
            float sx = 0.f, sy = 0.f;
            int cur = gid[pbeg]; int cnt = 0;
            for (int i = pbeg; i < pend; i++) {
                int g = gid[i];
                if (g != cur) {
                    atomicAdd(&g_gsum[cur * 64 + lane * 2], sx);
                    atomicAdd(&g_gsum[cur * 64 + lane * 2 + 1], sy);
                    if (lane == 0) atomicAdd(&g_gcnt[cur], cnt);
                    sx = 0.f; sy = 0.f; cnt = 0; cur = g;
                }
                float2 v = *(const float2*)(g_B4 + (size_t)i * 64 + lane * 2);
                sx += v.x; sy += v.y; cnt++;
            }
            atomicAdd(&g_gsum[cur * 64 + lane * 2], sx);
            atomicAdd(&g_gsum[cur * 64 + lane * 2 + 1], sy);
            if (lane == 0) atomicAdd(&g_gcnt[cur], cnt);
        }
    }
    gsync(nb);

    // ---- Finalize: write output + reset g_deg for next replay ----
    for (int i = gtid; i < G * 64; i += nthreads) {
        int c = g_gcnt[i >> 6];
        out[i] = g_gsum[i] / (c > 0 ? (float)c : 1.0f);
    }
    for (int i = gtid; i < n; i += nthreads) g_deg[i] = 0;
}

// ---------------- launch ----------------
extern "C" void kernel_launch(void* const* d_in, const int* in_sizes, int n_in,
                              void* d_out, int out_size) {
    const float* feat = (const float*)d_in[0];
    const int*   src  = (const int*)d_in[1];
    const int*   dst  = (const int*)d_in[2];
    const int*   gid  = (const int*)d_in[3];
    const float* W1 = (const float*)d_in[4];  const float* b1 = (const float*)d_in[5];
    const float* W2 = (const float*)d_in[6];  const float* b2 = (const float*)d_in[7];
    const float* W3 = (const float*)d_in[8];  const float* b3 = (const float*)d_in[9];
    const float* Wt1 = (const float*)d_in[10]; const float* bt1 = (const float*)d_in[11];
    const float* Wp1 = (const float*)d_in[12]; const float* bp1 = (const float*)d_in[13];
    const float* Wt2 = (const float*)d_in[14]; const float* bt2 = (const float*)d_in[15];
    const float* Wp2 = (const float*)d_in[16]; const float* bp2 = (const float*)d_in[17];
    float* out = (float*)d_out;

    const int n = in_sizes[0] / 16;
    const int e = in_sizes[1];
    const int G = out_size / 64;

    int dev = 0;
    cudaGetDevice(&dev);
    int sms = 0;
    cudaDeviceGetAttribute(&sms, cudaDevAttrMultiProcessorCount, dev);
    if (sms <= 0) sms = 148;
    int perSM = 0;
    cudaOccupancyMaxActiveBlocksPerMultiprocessor(&perSM, mega_kernel, 256, 0);
    if (perSM <= 0) perSM = 1;
    int grid = sms * perSM;
    if (grid > MAXB) grid = MAXB;

    mega_kernel<<<grid, 256>>>(feat, src, dst, gid,
                               W1, b1, W2, b2, W3, b3,
                               Wt1, bt1, Wp1, bp1, Wt2, bt2, Wp2, bp2,
                               out, n, e, G);
}